// round 4
// baseline (speedup 1.0000x reference)
#include <cuda_runtime.h>
#include <cuda_bf16.h>
#include <math.h>
#include <stdint.h>

#define NN 4096
#define GG 1024
#define HH1 512
#define HH2 64
#define NHEAD 4
#define CHAN 128
#define SEDIM 16
#define CAP 256
#define KP_DEC 128

// ---------------- scratch (static device globals; no allocation) ----------
__device__ __nv_bfloat16 g_Ahi[NN * HH1];  // activation hi (bf16 split)
__device__ __nv_bfloat16 g_Alo[NN * HH1];  // activation lo
__device__ __nv_bfloat16 g_Bhi[GG * HH1];  // weight hi, [n][k] K-major
__device__ __nv_bfloat16 g_Blo[GG * HH1];
__device__ float g_Hpre[NN * HH1];
__device__ float g_f1[NHEAD * NN];
__device__ float g_f2[NHEAD * NN];
__device__ int   g_cols[NN * CAP];
__device__ int   g_cnt[NN];

// ---------------- helpers ---------------------------------------------------
__device__ __forceinline__ void bsplit(float x, __nv_bfloat16* h, __nv_bfloat16* l) {
    __nv_bfloat16 hh = __float2bfloat16_rn(x);
    *h = hh;
    *l = __float2bfloat16_rn(x - __bfloat162float(hh));
}
__device__ __forceinline__ uint32_t bpack(float x, float y) {
    __nv_bfloat162 v = __floats2bfloat162_rn(x, y);
    return *reinterpret_cast<uint32_t*>(&v);
}
// split 8 fp32 -> packed bf16 hi uint4 + lo uint4
__device__ __forceinline__ void cvt8(const float4 a, const float4 b, uint4& hi, uint4& lo) {
    __nv_bfloat162 h0 = __floats2bfloat162_rn(a.x, a.y);
    __nv_bfloat162 h1 = __floats2bfloat162_rn(a.z, a.w);
    __nv_bfloat162 h2 = __floats2bfloat162_rn(b.x, b.y);
    __nv_bfloat162 h3 = __floats2bfloat162_rn(b.z, b.w);
    hi.x = *reinterpret_cast<uint32_t*>(&h0);
    hi.y = *reinterpret_cast<uint32_t*>(&h1);
    hi.z = *reinterpret_cast<uint32_t*>(&h2);
    hi.w = *reinterpret_cast<uint32_t*>(&h3);
    float2 f0 = __bfloat1622float2(h0), f1 = __bfloat1622float2(h1);
    float2 f2 = __bfloat1622float2(h2), f3 = __bfloat1622float2(h3);
    lo.x = bpack(a.x - f0.x, a.y - f0.y);
    lo.y = bpack(a.z - f1.x, a.w - f1.y);
    lo.z = bpack(b.x - f2.x, b.y - f2.y);
    lo.w = bpack(b.z - f3.x, b.w - f3.y);
}
__device__ __forceinline__ uint32_t smem_u32(const void* p) {
    uint32_t a;
    asm("{ .reg .u64 t; cvta.to.shared.u64 t, %1; cvt.u32.u64 %0, t; }" : "=r"(a) : "l"(p));
    return a;
}
#define LDM4(r, addr) \
    asm volatile("ldmatrix.sync.aligned.m8n8.x4.shared.b16 {%0,%1,%2,%3}, [%4];" \
                 : "=r"((r)[0]), "=r"((r)[1]), "=r"((r)[2]), "=r"((r)[3]) : "r"(addr))
#define MMA16816(d, a, b0_, b1_) \
    asm volatile("mma.sync.aligned.m16n8k16.row.col.f32.bf16.bf16.f32 " \
                 "{%0,%1,%2,%3}, {%4,%5,%6,%7}, {%8,%9}, {%0,%1,%2,%3};" \
                 : "+f"((d)[0]), "+f"((d)[1]), "+f"((d)[2]), "+f"((d)[3]) \
                 : "r"((a)[0]), "r"((a)[1]), "r"((a)[2]), "r"((a)[3]), "r"(b0_), "r"(b1_))

// ---------------- CSR build from dense adjacency ---------------------------
__global__ void build_csr(const float* __restrict__ adj) {
    int row = blockIdx.x;
    __shared__ int cnt;
    if (threadIdx.x == 0) cnt = 0;
    __syncthreads();
    const float4* arow = (const float4*)(adj + (size_t)row * NN);
    for (int j4 = threadIdx.x; j4 < NN / 4; j4 += blockDim.x) {
        float4 v = arow[j4];
        if (v.x != 0.f) { int k = atomicAdd(&cnt, 1); if (k < CAP) g_cols[row * CAP + k] = j4 * 4 + 0; }
        if (v.y != 0.f) { int k = atomicAdd(&cnt, 1); if (k < CAP) g_cols[row * CAP + k] = j4 * 4 + 1; }
        if (v.z != 0.f) { int k = atomicAdd(&cnt, 1); if (k < CAP) g_cols[row * CAP + k] = j4 * 4 + 2; }
        if (v.w != 0.f) { int k = atomicAdd(&cnt, 1); if (k < CAP) g_cols[row * CAP + k] = j4 * 4 + 3; }
    }
    __syncthreads();
    if (threadIdx.x == 0) g_cnt[row] = min(cnt, CAP);
}

// ---------------- pack [NH,K,CH] head weights -> B[n=512][KPad] + split -----
__global__ void pack_headsB(const float* __restrict__ W, int K, int KPad) {
    int idx = blockIdx.x * blockDim.x + threadIdx.x;
    if (idx >= HH1 * KPad) return;
    int n = idx / KPad, k = idx - n * KPad;
    int h = n >> 7, c = n & 127;
    float v = (k < K) ? W[((size_t)h * K + k) * CHAN + c] : 0.f;
    bsplit(v, &g_Bhi[idx], &g_Blo[idx]);
}

// ---------------- transpose W[K,Nc] -> B[Nc][K] + split ---------------------
__global__ void pack_tB(const float* __restrict__ W, int K, int Nc) {
    int idx = blockIdx.x * blockDim.x + threadIdx.x;
    if (idx >= K * Nc) return;
    int k = idx / Nc, n = idx - k * Nc;
    bsplit(W[idx], &g_Bhi[(size_t)n * K + k], &g_Blo[(size_t)n * K + k]);
}

// ---------------- HMMA bf16-split GEMM, MTILE x NT tiles --------------------
// C[4096,Nc] = A[4096,K] @ B[Nc,K]^T + bias.  K % 32 == 0.
// AF32: A read as fp32 and split in the loader.  DOF: fused f1/f2 (NT==128).
template <int MTILE, int NT, bool AF32, bool DOF>
__global__ void __launch_bounds__(256)
gemm_hmma(const __nv_bfloat16* __restrict__ Ah, const __nv_bfloat16* __restrict__ Al,
          const float* __restrict__ Af, const float* __restrict__ bias,
          float* __restrict__ C, int K, int Nc,
          const float* __restrict__ v0, const float* __restrict__ v1) {
    constexpr int WMW = (MTILE == 128) ? 2 : 4;
    constexpr int WNW = 8 / WMW;
    constexpr int WM  = MTILE / WMW;
    constexpr int WN  = NT / WNW;
    constexpr int MT  = WM / 16;
    constexpr int NTL = WN / 8;
    constexpr int NP  = NTL / 2;
    constexpr int ASZ = MTILE * 80;
    constexpr int BSZ = NT * 80;
    constexpr int STG = 2 * ASZ + 2 * BSZ;
    constexpr int AJ  = MTILE / 64;
    constexpr int BJ  = NT / 64;

    extern __shared__ char sm[];
    const int tid = threadIdx.x, lane = tid & 31, wid = tid >> 5;
    const int m0 = blockIdx.y * MTILE, n0 = blockIdx.x * NT;
    const int wm0 = (wid % WMW) * WM, wn0 = (wid / WMW) * WN;

    const int ar = (AJ == 2) ? (tid >> 1) : (tid >> 2);
    const int ac = (AJ == 2) ? ((tid & 1) * 16) : ((tid & 3) * 8);
    const size_t abase = (size_t)(m0 + ar) * K + ac;
    const int br = (BJ == 2) ? (tid >> 1) : (tid >> 2);
    const int bc = (BJ == 2) ? ((tid & 1) * 16) : ((tid & 3) * 8);
    const size_t bbase = (size_t)(n0 + br) * K + bc;

    const uint32_t sA = smem_u32(sm);
    const uint32_t stA = ar * 80 + ac * 2;
    const uint32_t stB = br * 80 + bc * 2;

    const int lr = lane & 15, lk = (lane >> 4) * 8;
    const uint32_t aoff = (wm0 + lr) * 80 + lk * 2;
    const uint32_t boff = (wn0 + lr) * 80 + lk * 2;

    float acc[MT][NTL][4];
#pragma unroll
    for (int i = 0; i < MT; i++)
#pragma unroll
        for (int j = 0; j < NTL; j++)
#pragma unroll
            for (int q = 0; q < 4; q++) acc[i][j][q] = 0.f;

    const int NC = K >> 5;
    uint4 pAh[AJ], pAl[AJ], pBh[BJ], pBl[BJ];

#define GLOAD(c0)                                                              \
    {                                                                          \
        int k0 = (c0) * 32;                                                    \
        if (AF32) {                                                            \
            _Pragma("unroll") for (int j = 0; j < AJ; j++) {                   \
                float4 fa = *(const float4*)(Af + abase + k0 + j * 8);         \
                float4 fb = *(const float4*)(Af + abase + k0 + j * 8 + 4);     \
                cvt8(fa, fb, pAh[j], pAl[j]);                                  \
            }                                                                  \
        } else {                                                               \
            _Pragma("unroll") for (int j = 0; j < AJ; j++) {                   \
                pAh[j] = *(const uint4*)(Ah + abase + k0 + j * 8);             \
                pAl[j] = *(const uint4*)(Al + abase + k0 + j * 8);             \
            }                                                                  \
        }                                                                      \
        _Pragma("unroll") for (int j = 0; j < BJ; j++) {                       \
            pBh[j] = *(const uint4*)(g_Bhi + bbase + k0 + j * 8);              \
            pBl[j] = *(const uint4*)(g_Blo + bbase + k0 + j * 8);              \
        }                                                                      \
    }
#define SSTORE(buf)                                                            \
    {                                                                          \
        char* p = sm + (buf) * STG;                                            \
        _Pragma("unroll") for (int j = 0; j < AJ; j++) {                       \
            *(uint4*)(p + stA + j * 16) = pAh[j];                              \
            *(uint4*)(p + ASZ + stA + j * 16) = pAl[j];                        \
        }                                                                      \
        _Pragma("unroll") for (int j = 0; j < BJ; j++) {                       \
            *(uint4*)(p + 2 * ASZ + stB + j * 16) = pBh[j];                    \
            *(uint4*)(p + 2 * ASZ + BSZ + stB + j * 16) = pBl[j];              \
        }                                                                      \
    }

    GLOAD(0);
    SSTORE(0);
    for (int c = 0; c < NC; c++) {
        __syncthreads();
        if (c + 1 < NC) GLOAD(c + 1);
        uint32_t uAh = sA + (c & 1) * STG;
        uint32_t uAl = uAh + ASZ;
        uint32_t uBh = uAh + 2 * ASZ;
        uint32_t uBl = uBh + BSZ;
#pragma unroll
        for (int ks = 0; ks < 2; ks++) {
            uint32_t ah[MT][4], al[MT][4], bh[NP][4], bl[NP][4];
            // stage 1: hi fragments, then hi*hi MMAs (LDSM latency hidden by MMA issue)
#pragma unroll
            for (int mt = 0; mt < MT; mt++) LDM4(ah[mt], uAh + aoff + mt * 1280 + ks * 32);
#pragma unroll
            for (int p = 0; p < NP; p++) LDM4(bh[p], uBh + boff + p * 1280 + ks * 32);
#pragma unroll
            for (int mt = 0; mt < MT; mt++)
#pragma unroll
                for (int p = 0; p < NP; p++) {
                    MMA16816(acc[mt][2 * p],     ah[mt], bh[p][0], bh[p][2]);
                    MMA16816(acc[mt][2 * p + 1], ah[mt], bh[p][1], bh[p][3]);
                }
            // stage 2: lo-A fragments, lo*hi MMAs
#pragma unroll
            for (int mt = 0; mt < MT; mt++) LDM4(al[mt], uAl + aoff + mt * 1280 + ks * 32);
#pragma unroll
            for (int mt = 0; mt < MT; mt++)
#pragma unroll
                for (int p = 0; p < NP; p++) {
                    MMA16816(acc[mt][2 * p],     al[mt], bh[p][0], bh[p][2]);
                    MMA16816(acc[mt][2 * p + 1], al[mt], bh[p][1], bh[p][3]);
                }
            // stage 3: lo-B fragments, hi*lo MMAs
#pragma unroll
            for (int p = 0; p < NP; p++) LDM4(bl[p], uBl + boff + p * 1280 + ks * 32);
#pragma unroll
            for (int mt = 0; mt < MT; mt++)
#pragma unroll
                for (int p = 0; p < NP; p++) {
                    MMA16816(acc[mt][2 * p],     ah[mt], bl[p][0], bl[p][2]);
                    MMA16816(acc[mt][2 * p + 1], ah[mt], bl[p][1], bl[p][3]);
                }
        }
        if (c + 1 < NC) SSTORE((c + 1) & 1);
    }
#undef GLOAD
#undef SSTORE

    // ---------------- epilogue --------------------------------------------
    float* sf1 = (float*)sm;
    float* sf2 = sf1 + MTILE;
    if (DOF) {
        __syncthreads();               // everyone done with staging smem
        ((float*)sm)[tid] = 0.f;       // zero sf1[128]+sf2[128]
        __syncthreads();
    }

    int g = lane >> 2, tg = lane & 3;
    float v0c[NTL][2], v1c[NTL][2];
    if (DOF) {
#pragma unroll
        for (int nt = 0; nt < NTL; nt++) {
            int col = n0 + wn0 + nt * 8 + tg * 2;
            v0c[nt][0] = v0[col]; v0c[nt][1] = v0[col + 1];
            v1c[nt][0] = v1[col]; v1c[nt][1] = v1[col + 1];
        }
    }
#pragma unroll
    for (int mt = 0; mt < MT; mt++) {
        int row = m0 + wm0 + mt * 16 + g;
        float fa0 = 0.f, fb0 = 0.f, fa8 = 0.f, fb8 = 0.f;
#pragma unroll
        for (int nt = 0; nt < NTL; nt++) {
            int col = n0 + wn0 + nt * 8 + tg * 2;
            float b0 = bias[col], b1 = bias[col + 1];
            float c0 = acc[mt][nt][0] + b0, c1 = acc[mt][nt][1] + b1;
            float c2 = acc[mt][nt][2] + b0, c3 = acc[mt][nt][3] + b1;
            C[(size_t)row * Nc + col]           = c0;
            C[(size_t)row * Nc + col + 1]       = c1;
            C[(size_t)(row + 8) * Nc + col]     = c2;
            C[(size_t)(row + 8) * Nc + col + 1] = c3;
            if (DOF) {
                fa0 += c0 * v0c[nt][0] + c1 * v0c[nt][1];
                fb0 += c0 * v1c[nt][0] + c1 * v1c[nt][1];
                fa8 += c2 * v0c[nt][0] + c3 * v0c[nt][1];
                fb8 += c2 * v1c[nt][0] + c3 * v1c[nt][1];
            }
        }
        if (DOF) {
            int rl = wm0 + mt * 16 + g;
            atomicAdd(&sf1[rl], fa0);     atomicAdd(&sf2[rl], fb0);
            atomicAdd(&sf1[rl + 8], fa8); atomicAdd(&sf2[rl + 8], fb8);
        }
    }
    if (DOF) {
        __syncthreads();
        if (tid < MTILE) {
            int h = blockIdx.x;           // NT==128, Nc==512 -> tile == head
            g_f1[h * NN + m0 + tid] = sf1[tid];
            g_f2[h * NN + m0 + tid] = sf2[tid];
        }
    }
}

// ---------------- sparse attention softmax + aggregation + ELU -------------
// block = one row, warp = one head; writes bf16 hi/lo split for next GEMM
__global__ void __launch_bounds__(128) gat_agg2(const float* __restrict__ Hpre) {
    int row = blockIdx.x, tid = threadIdx.x, wid = tid >> 5, lid = tid & 31;
    int cnt = g_cnt[row];
    __shared__ int sc[CAP];
    __shared__ float sw[NHEAD][CAP];
    for (int k = tid; k < cnt; k += 128) sc[k] = g_cols[row * CAP + k];
    __syncthreads();

    float f1r = g_f1[wid * NN + row];
    float mx = -1e30f;
    for (int k = lid; k < cnt; k += 32) {
        float x = f1r + g_f2[wid * NN + sc[k]];
        float u = 1.f / (1.f + expf(-x)) - 0.5f;
        sw[wid][k] = u;
        if (u != 0.f) mx = fmaxf(mx, u);
    }
#pragma unroll
    for (int o = 16; o; o >>= 1) mx = fmaxf(mx, __shfl_xor_sync(0xffffffffu, mx, o));
    __syncwarp();
    float s = 0.f;
    for (int k = lid; k < cnt; k += 32) {
        float u = sw[wid][k];
        float e = (u != 0.f) ? expf(u - mx) : 0.f;
        sw[wid][k] = e;
        s += e;
    }
#pragma unroll
    for (int o = 16; o; o >>= 1) s += __shfl_xor_sync(0xffffffffu, s, o);
    float inv = 1.f / fmaxf(s, 1e-30f);
    __syncwarp();

    float4 acc = {0.f, 0.f, 0.f, 0.f};
    const float* Hb = Hpre + wid * CHAN + lid * 4;
    for (int k = 0; k < cnt; k++) {
        float w = sw[wid][k];
        float4 hv = *(const float4*)(Hb + (size_t)sc[k] * HH1);
        acc.x += w * hv.x; acc.y += w * hv.y; acc.z += w * hv.z; acc.w += w * hv.w;
    }
    acc.x *= inv; acc.y *= inv; acc.z *= inv; acc.w *= inv;
    acc.x = (acc.x > 0.f) ? acc.x : expm1f(acc.x);
    acc.y = (acc.y > 0.f) ? acc.y : expm1f(acc.y);
    acc.z = (acc.z > 0.f) ? acc.z : expm1f(acc.z);
    acc.w = (acc.w > 0.f) ? acc.w : expm1f(acc.w);
    size_t base = (size_t)row * HH1 + wid * CHAN + lid * 4;
    bsplit(acc.x, &g_Ahi[base + 0], &g_Alo[base + 0]);
    bsplit(acc.y, &g_Ahi[base + 1], &g_Alo[base + 1]);
    bsplit(acc.z, &g_Ahi[base + 2], &g_Alo[base + 2]);
    bsplit(acc.w, &g_Ahi[base + 3], &g_Alo[base + 3]);
}

// ---------------- Hd = concat(Z, emb[slice], zero-pad to 128), split -------
__global__ void build_hd(const float* __restrict__ Z,
                         const int* __restrict__ slice,
                         const float* __restrict__ emb) {
    int n = blockIdx.x, t = threadIdx.x;  // 128 threads
    float v = 0.f;
    if (t < HH2) v = Z[(size_t)n * HH2 + t];
    else if (t < HH2 + SEDIM) v = emb[slice[n] * SEDIM + (t - HH2)];
    bsplit(v, &g_Ahi[(size_t)n * KP_DEC + t], &g_Alo[(size_t)n * KP_DEC + t]);
}

extern "C" void kernel_launch(void* const* d_in, const int* in_sizes, int n_in,
                              void* d_out, int out_size) {
    const float* adj     = (const float*)d_in[0];
    const float* node    = (const float*)d_in[1];
    const int*   slice   = (const int*)d_in[4];
    const float* enc1_W  = (const float*)d_in[6];
    const float* enc1_b  = (const float*)d_in[7];
    const float* enc1_v0 = (const float*)d_in[8];
    const float* enc1_v1 = (const float*)d_in[9];
    const float* enc2_W  = (const float*)d_in[10];
    const float* enc2_b  = (const float*)d_in[11];
    const float* dec1_W  = (const float*)d_in[12];
    const float* dec1_b  = (const float*)d_in[13];
    const float* dec1_v0 = (const float*)d_in[14];
    const float* dec1_v1 = (const float*)d_in[15];
    const float* dec2_W  = (const float*)d_in[16];
    const float* dec2_b  = (const float*)d_in[17];
    const float* emb     = (const float*)d_in[18];

    float* out_recon = (float*)d_out;                   // [N, G]
    float* out_Z     = (float*)d_out + (size_t)NN * GG; // [N, H2]

    float* Hpre; cudaGetSymbolAddress((void**)&Hpre, g_Hpre);
    __nv_bfloat16* Ahi; cudaGetSymbolAddress((void**)&Ahi, g_Ahi);
    __nv_bfloat16* Alo; cudaGetSymbolAddress((void**)&Alo, g_Alo);

    const int SMBIG = 2 * (2 * 128 * 80 + 2 * 128 * 80); // 81920
    const int SMZ   = 2 * (2 * 64 * 80 + 2 * 64 * 80);   // 40960
    cudaFuncSetAttribute((const void*)gemm_hmma<128, 128, true, true>,
                         cudaFuncAttributeMaxDynamicSharedMemorySize, SMBIG);
    cudaFuncSetAttribute((const void*)gemm_hmma<128, 128, false, true>,
                         cudaFuncAttributeMaxDynamicSharedMemorySize, SMBIG);
    cudaFuncSetAttribute((const void*)gemm_hmma<128, 128, false, false>,
                         cudaFuncAttributeMaxDynamicSharedMemorySize, SMBIG);
    cudaFuncSetAttribute((const void*)gemm_hmma<64, 64, false, false>,
                         cudaFuncAttributeMaxDynamicSharedMemorySize, SMZ);

    // 1. dense adj -> per-row column lists
    build_csr<<<NN, 256>>>(adj);

    // 2. encoder GAT layer 1 (A = fp32 node feats, split inline; feats fused)
    pack_headsB<<<(HH1 * GG + 255) / 256, 256>>>(enc1_W, GG, GG);
    gemm_hmma<128, 128, true, true><<<dim3(4, 32), 256, SMBIG>>>(
        nullptr, nullptr, node, enc1_b, Hpre, GG, HH1, enc1_v0, enc1_v1);
    gat_agg2<<<NN, 128>>>(Hpre);   // -> g_Ahi/g_Alo [4096,512]

    // 3. Z = Hagg @ enc2_W + b (straight to output tail)
    pack_tB<<<(HH1 * HH2 + 255) / 256, 256>>>(enc2_W, HH1, HH2);
    gemm_hmma<64, 64, false, false><<<dim3(1, 64), 256, SMZ>>>(
        Ahi, Alo, nullptr, enc2_b, out_Z, HH1, HH2, nullptr, nullptr);

    // 4. decoder GAT layer (K padded 80 -> 128; feats fused)
    build_hd<<<NN, 128>>>(out_Z, slice, emb);   // -> g_Ahi/g_Alo [4096,128]
    pack_headsB<<<(HH1 * KP_DEC + 255) / 256, 256>>>(dec1_W, HH2 + SEDIM, KP_DEC);
    gemm_hmma<128, 128, false, true><<<dim3(4, 32), 256, SMBIG>>>(
        Ahi, Alo, nullptr, dec1_b, Hpre, KP_DEC, HH1, dec1_v0, dec1_v1);
    gat_agg2<<<NN, 128>>>(Hpre);   // -> g_Ahi/g_Alo [4096,512]

    // 5. recon = Hagg @ dec2_W + b
    pack_tB<<<(HH1 * GG + 255) / 256, 256>>>(dec2_W, HH1, GG);
    gemm_hmma<128, 128, false, false><<<dim3(8, 32), 256, SMBIG>>>(
        Ahi, Alo, nullptr, dec2_b, out_recon, HH1, GG, nullptr, nullptr);
}

// round 5
// speedup vs baseline: 1.4765x; 1.4765x over previous
#include <cuda_runtime.h>
#include <cuda_bf16.h>
#include <math.h>
#include <stdint.h>

#define NN 4096
#define GG 1024
#define HH1 512
#define HH2 64
#define NHEAD 4
#define CHAN 128
#define SEDIM 16
#define CAP 256
#define KP_DEC 128

// ---------------- scratch (static device globals; no allocation) ----------
__device__ __nv_bfloat16 g_Ahi[NN * GG];   // activation hi (bf16 split)
__device__ __nv_bfloat16 g_Alo[NN * GG];   // activation lo
__device__ __nv_bfloat16 g_Bhi[GG * HH1];  // weight hi, [n][k] K-major
__device__ __nv_bfloat16 g_Blo[GG * HH1];
__device__ float g_Hpre[NN * HH1];
__device__ float g_f1[NHEAD * NN];
__device__ float g_f2[NHEAD * NN];
__device__ int   g_cols[NN * CAP];
__device__ int   g_cnt[NN];

// ---------------- helpers ---------------------------------------------------
__device__ __forceinline__ void bsplit(float x, __nv_bfloat16* h, __nv_bfloat16* l) {
    __nv_bfloat16 hh = __float2bfloat16_rn(x);
    *h = hh;
    *l = __float2bfloat16_rn(x - __bfloat162float(hh));
}
__device__ __forceinline__ uint32_t smem_u32(const void* p) {
    uint32_t a;
    asm("{ .reg .u64 t; cvta.to.shared.u64 t, %1; cvt.u32.u64 %0, t; }" : "=r"(a) : "l"(p));
    return a;
}
#define LDM4(r, addr) \
    asm volatile("ldmatrix.sync.aligned.m8n8.x4.shared.b16 {%0,%1,%2,%3}, [%4];" \
                 : "=r"((r)[0]), "=r"((r)[1]), "=r"((r)[2]), "=r"((r)[3]) : "r"(addr))
#define MMA16816(d, a, b0_, b1_) \
    asm volatile("mma.sync.aligned.m16n8k16.row.col.f32.bf16.bf16.f32 " \
                 "{%0,%1,%2,%3}, {%4,%5,%6,%7}, {%8,%9}, {%0,%1,%2,%3};" \
                 : "+f"((d)[0]), "+f"((d)[1]), "+f"((d)[2]), "+f"((d)[3]) \
                 : "r"((a)[0]), "r"((a)[1]), "r"((a)[2]), "r"((a)[3]), "r"(b0_), "r"(b1_))

// ---------------- CSR build from dense adjacency ---------------------------
__global__ void build_csr(const float* __restrict__ adj) {
    int row = blockIdx.x;
    __shared__ int cnt;
    if (threadIdx.x == 0) cnt = 0;
    __syncthreads();
    const float4* arow = (const float4*)(adj + (size_t)row * NN);
    for (int j4 = threadIdx.x; j4 < NN / 4; j4 += blockDim.x) {
        float4 v = arow[j4];
        if (v.x != 0.f) { int k = atomicAdd(&cnt, 1); if (k < CAP) g_cols[row * CAP + k] = j4 * 4 + 0; }
        if (v.y != 0.f) { int k = atomicAdd(&cnt, 1); if (k < CAP) g_cols[row * CAP + k] = j4 * 4 + 1; }
        if (v.z != 0.f) { int k = atomicAdd(&cnt, 1); if (k < CAP) g_cols[row * CAP + k] = j4 * 4 + 2; }
        if (v.w != 0.f) { int k = atomicAdd(&cnt, 1); if (k < CAP) g_cols[row * CAP + k] = j4 * 4 + 3; }
    }
    __syncthreads();
    if (threadIdx.x == 0) g_cnt[row] = min(cnt, CAP);
}

// ---------------- split node feats into bf16 hi/lo --------------------------
__global__ void cvt_node(const float4* __restrict__ x) {
    int i = blockIdx.x * blockDim.x + threadIdx.x;  // over NN*GG/4
    float4 v = x[i];
    int b = i * 4;
    bsplit(v.x, &g_Ahi[b + 0], &g_Alo[b + 0]);
    bsplit(v.y, &g_Ahi[b + 1], &g_Alo[b + 1]);
    bsplit(v.z, &g_Ahi[b + 2], &g_Alo[b + 2]);
    bsplit(v.w, &g_Ahi[b + 3], &g_Alo[b + 3]);
}

// ---------------- pack [NH,K,CH] head weights -> B[n=512][KPad] + split -----
__global__ void pack_headsB(const float* __restrict__ W, int K, int KPad) {
    int idx = blockIdx.x * blockDim.x + threadIdx.x;
    if (idx >= HH1 * KPad) return;
    int n = idx / KPad, k = idx - n * KPad;
    int h = n >> 7, c = n & 127;
    float v = (k < K) ? W[((size_t)h * K + k) * CHAN + c] : 0.f;
    bsplit(v, &g_Bhi[idx], &g_Blo[idx]);
}

// ---------------- transpose W[K,Nc] -> B[Nc][K] + split ---------------------
__global__ void pack_tB(const float* __restrict__ W, int K, int Nc) {
    int idx = blockIdx.x * blockDim.x + threadIdx.x;
    if (idx >= K * Nc) return;
    int k = idx / Nc, n = idx - k * Nc;
    bsplit(W[idx], &g_Bhi[(size_t)n * K + k], &g_Blo[(size_t)n * K + k]);
}

// ---------------- HMMA bf16-split GEMM, MTILE x NT tiles --------------------
// C[4096,Nc] = (Ahi+Alo)[4096,K] @ (Bhi+Blo)[Nc,K]^T + bias.  K % 32 == 0.
// Round-3 proven schedule: batched global loads, batched LDSM, 3 term blocks.
// NT=64 + launch_bounds(256,2) -> 2 CTAs/SM for latency hiding.
template <int MTILE, int NT>
__global__ void __launch_bounds__(256, 2)
gemm_hmma(const __nv_bfloat16* __restrict__ Ah, const __nv_bfloat16* __restrict__ Al,
          const float* __restrict__ bias, float* __restrict__ C, int K, int Nc) {
    constexpr int WMW = (MTILE == 128) ? 2 : 4;   // warps along m
    constexpr int WNW = 8 / WMW;                  // warps along n
    constexpr int WM  = MTILE / WMW;
    constexpr int WN  = NT / WNW;
    constexpr int MT  = WM / 16;
    constexpr int NTL = WN / 8;
    constexpr int NP  = NTL / 2;
    constexpr int ASZ = MTILE * 80;               // bytes per tile (stride 80)
    constexpr int BSZ = NT * 80;
    constexpr int STG = 2 * ASZ + 2 * BSZ;
    constexpr int AJ  = MTILE / 64;               // uint4 per thread for A
    constexpr int BJ  = (NT >= 64) ? NT / 64 : 1;

    extern __shared__ char sm[];
    const int tid = threadIdx.x, lane = tid & 31, wid = tid >> 5;
    const int m0 = blockIdx.y * MTILE, n0 = blockIdx.x * NT;
    const int wm0 = (wid % WMW) * WM, wn0 = (wid / WMW) * WN;

    const int ar = (AJ == 2) ? (tid >> 1) : (tid >> 2);
    const int ac = (AJ == 2) ? ((tid & 1) * 16) : ((tid & 3) * 8);
    const size_t abase = (size_t)(m0 + ar) * K + ac;
    const int br = (BJ == 2) ? (tid >> 1) : (tid >> 2);
    const int bc = (BJ == 2) ? ((tid & 1) * 16) : ((tid & 3) * 8);
    const size_t bbase = (size_t)(n0 + br) * K + bc;

    const uint32_t sA = smem_u32(sm);
    const uint32_t stA = ar * 80 + ac * 2;
    const uint32_t stB = br * 80 + bc * 2;

    const int lr = lane & 15, lk = (lane >> 4) * 8;
    const uint32_t aoff = (wm0 + lr) * 80 + lk * 2;
    const uint32_t boff = (wn0 + lr) * 80 + lk * 2;

    float acc[MT][NTL][4];
#pragma unroll
    for (int i = 0; i < MT; i++)
#pragma unroll
        for (int j = 0; j < NTL; j++)
#pragma unroll
            for (int q = 0; q < 4; q++) acc[i][j][q] = 0.f;

    const int NC = K >> 5;
    uint4 pAh[AJ], pAl[AJ], pBh[BJ], pBl[BJ];

#define GLOAD(c0)                                                              \
    {                                                                          \
        int k0 = (c0) * 32;                                                    \
        _Pragma("unroll") for (int j = 0; j < AJ; j++) {                       \
            pAh[j] = *(const uint4*)(Ah + abase + k0 + j * 8);                 \
            pAl[j] = *(const uint4*)(Al + abase + k0 + j * 8);                 \
        }                                                                      \
        _Pragma("unroll") for (int j = 0; j < BJ; j++) {                       \
            pBh[j] = *(const uint4*)(g_Bhi + bbase + k0 + j * 8);              \
            pBl[j] = *(const uint4*)(g_Blo + bbase + k0 + j * 8);              \
        }                                                                      \
    }
#define SSTORE(buf)                                                            \
    {                                                                          \
        char* p = sm + (buf) * STG;                                            \
        _Pragma("unroll") for (int j = 0; j < AJ; j++) {                       \
            *(uint4*)(p + stA + j * 16) = pAh[j];                              \
            *(uint4*)(p + ASZ + stA + j * 16) = pAl[j];                        \
        }                                                                      \
        _Pragma("unroll") for (int j = 0; j < BJ; j++) {                       \
            *(uint4*)(p + 2 * ASZ + stB + j * 16) = pBh[j];                    \
            *(uint4*)(p + 2 * ASZ + BSZ + stB + j * 16) = pBl[j];              \
        }                                                                      \
    }

    GLOAD(0);
    SSTORE(0);
    for (int c = 0; c < NC; c++) {
        __syncthreads();
        if (c + 1 < NC) GLOAD(c + 1);
        uint32_t uAh = sA + (c & 1) * STG;
        uint32_t uAl = uAh + ASZ;
        uint32_t uBh = uAh + 2 * ASZ;
        uint32_t uBl = uBh + BSZ;
#pragma unroll
        for (int ks = 0; ks < 2; ks++) {
            uint32_t ah[MT][4], al[MT][4], bh[NP][4], bl[NP][4];
#pragma unroll
            for (int mt = 0; mt < MT; mt++) LDM4(ah[mt], uAh + aoff + mt * 1280 + ks * 32);
#pragma unroll
            for (int mt = 0; mt < MT; mt++) LDM4(al[mt], uAl + aoff + mt * 1280 + ks * 32);
#pragma unroll
            for (int p = 0; p < NP; p++) LDM4(bh[p], uBh + boff + p * 1280 + ks * 32);
#pragma unroll
            for (int p = 0; p < NP; p++) LDM4(bl[p], uBl + boff + p * 1280 + ks * 32);
            // term 1: hi*hi
#pragma unroll
            for (int mt = 0; mt < MT; mt++)
#pragma unroll
                for (int p = 0; p < NP; p++) {
                    MMA16816(acc[mt][2 * p],     ah[mt], bh[p][0], bh[p][2]);
                    MMA16816(acc[mt][2 * p + 1], ah[mt], bh[p][1], bh[p][3]);
                }
            // term 2: hi*lo
#pragma unroll
            for (int mt = 0; mt < MT; mt++)
#pragma unroll
                for (int p = 0; p < NP; p++) {
                    MMA16816(acc[mt][2 * p],     ah[mt], bl[p][0], bl[p][2]);
                    MMA16816(acc[mt][2 * p + 1], ah[mt], bl[p][1], bl[p][3]);
                }
            // term 3: lo*hi
#pragma unroll
            for (int mt = 0; mt < MT; mt++)
#pragma unroll
                for (int p = 0; p < NP; p++) {
                    MMA16816(acc[mt][2 * p],     al[mt], bh[p][0], bh[p][2]);
                    MMA16816(acc[mt][2 * p + 1], al[mt], bh[p][1], bh[p][3]);
                }
        }
        if (c + 1 < NC) SSTORE((c + 1) & 1);
    }
#undef GLOAD
#undef SSTORE

    // epilogue: bias + store
    int g = lane >> 2, tg = lane & 3;
#pragma unroll
    for (int mt = 0; mt < MT; mt++) {
        int row = m0 + wm0 + mt * 16 + g;
#pragma unroll
        for (int nt = 0; nt < NTL; nt++) {
            int col = n0 + wn0 + nt * 8 + tg * 2;
            float b0 = bias[col], b1 = bias[col + 1];
            C[(size_t)row * Nc + col]           = acc[mt][nt][0] + b0;
            C[(size_t)row * Nc + col + 1]       = acc[mt][nt][1] + b1;
            C[(size_t)(row + 8) * Nc + col]     = acc[mt][nt][2] + b0;
            C[(size_t)(row + 8) * Nc + col + 1] = acc[mt][nt][3] + b1;
        }
    }
}

// ---------------- attention features f1 = h@v0, f2 = h@v1 ------------------
__global__ void feats(const float* __restrict__ Hpre,
                      const float* __restrict__ v0,
                      const float* __restrict__ v1) {
    int n = blockIdx.x;
    int w = threadIdx.x / 32;
    int l = threadIdx.x % 32;
    float4 hv = *(const float4*)(Hpre + (size_t)n * HH1 + w * CHAN + l * 4);
    float4 a  = *(const float4*)(v0 + w * CHAN + l * 4);
    float4 b  = *(const float4*)(v1 + w * CHAN + l * 4);
    float s1 = hv.x * a.x + hv.y * a.y + hv.z * a.z + hv.w * a.w;
    float s2 = hv.x * b.x + hv.y * b.y + hv.z * b.z + hv.w * b.w;
#pragma unroll
    for (int o = 16; o > 0; o >>= 1) {
        s1 += __shfl_down_sync(0xffffffffu, s1, o);
        s2 += __shfl_down_sync(0xffffffffu, s2, o);
    }
    if (l == 0) {
        g_f1[w * NN + n] = s1;
        g_f2[w * NN + n] = s2;
    }
}

// ---------------- sparse attention softmax + aggregation + ELU -------------
// block = one row, warp = one head; writes bf16 hi/lo split for next GEMM
__global__ void __launch_bounds__(128) gat_agg2(const float* __restrict__ Hpre) {
    int row = blockIdx.x, tid = threadIdx.x, wid = tid >> 5, lid = tid & 31;
    int cnt = g_cnt[row];
    __shared__ int sc[CAP];
    __shared__ float sw[NHEAD][CAP];
    for (int k = tid; k < cnt; k += 128) sc[k] = g_cols[row * CAP + k];
    __syncthreads();

    float f1r = g_f1[wid * NN + row];
    float mx = -1e30f;
    for (int k = lid; k < cnt; k += 32) {
        float x = f1r + g_f2[wid * NN + sc[k]];
        float u = 1.f / (1.f + expf(-x)) - 0.5f;
        sw[wid][k] = u;
        if (u != 0.f) mx = fmaxf(mx, u);
    }
#pragma unroll
    for (int o = 16; o; o >>= 1) mx = fmaxf(mx, __shfl_xor_sync(0xffffffffu, mx, o));
    __syncwarp();
    float s = 0.f;
    for (int k = lid; k < cnt; k += 32) {
        float u = sw[wid][k];
        float e = (u != 0.f) ? expf(u - mx) : 0.f;
        sw[wid][k] = e;
        s += e;
    }
#pragma unroll
    for (int o = 16; o; o >>= 1) s += __shfl_xor_sync(0xffffffffu, s, o);
    float inv = 1.f / fmaxf(s, 1e-30f);
    __syncwarp();

    float4 acc = {0.f, 0.f, 0.f, 0.f};
    const float* Hb = Hpre + wid * CHAN + lid * 4;
    for (int k = 0; k < cnt; k++) {
        float w = sw[wid][k];
        float4 hv = *(const float4*)(Hb + (size_t)sc[k] * HH1);
        acc.x += w * hv.x; acc.y += w * hv.y; acc.z += w * hv.z; acc.w += w * hv.w;
    }
    acc.x *= inv; acc.y *= inv; acc.z *= inv; acc.w *= inv;
    acc.x = (acc.x > 0.f) ? acc.x : expm1f(acc.x);
    acc.y = (acc.y > 0.f) ? acc.y : expm1f(acc.y);
    acc.z = (acc.z > 0.f) ? acc.z : expm1f(acc.z);
    acc.w = (acc.w > 0.f) ? acc.w : expm1f(acc.w);
    size_t base = (size_t)row * HH1 + wid * CHAN + lid * 4;
    bsplit(acc.x, &g_Ahi[base + 0], &g_Alo[base + 0]);
    bsplit(acc.y, &g_Ahi[base + 1], &g_Alo[base + 1]);
    bsplit(acc.z, &g_Ahi[base + 2], &g_Alo[base + 2]);
    bsplit(acc.w, &g_Ahi[base + 3], &g_Alo[base + 3]);
}

// ---------------- Hd = concat(Z, emb[slice], zero-pad to 128), split -------
__global__ void build_hd(const float* __restrict__ Z,
                         const int* __restrict__ slice,
                         const float* __restrict__ emb) {
    int n = blockIdx.x, t = threadIdx.x;  // 128 threads
    float v = 0.f;
    if (t < HH2) v = Z[(size_t)n * HH2 + t];
    else if (t < HH2 + SEDIM) v = emb[slice[n] * SEDIM + (t - HH2)];
    bsplit(v, &g_Ahi[(size_t)n * KP_DEC + t], &g_Alo[(size_t)n * KP_DEC + t]);
}

extern "C" void kernel_launch(void* const* d_in, const int* in_sizes, int n_in,
                              void* d_out, int out_size) {
    const float* adj     = (const float*)d_in[0];
    const float* node    = (const float*)d_in[1];
    const int*   slice   = (const int*)d_in[4];
    const float* enc1_W  = (const float*)d_in[6];
    const float* enc1_b  = (const float*)d_in[7];
    const float* enc1_v0 = (const float*)d_in[8];
    const float* enc1_v1 = (const float*)d_in[9];
    const float* enc2_W  = (const float*)d_in[10];
    const float* enc2_b  = (const float*)d_in[11];
    const float* dec1_W  = (const float*)d_in[12];
    const float* dec1_b  = (const float*)d_in[13];
    const float* dec1_v0 = (const float*)d_in[14];
    const float* dec1_v1 = (const float*)d_in[15];
    const float* dec2_W  = (const float*)d_in[16];
    const float* dec2_b  = (const float*)d_in[17];
    const float* emb     = (const float*)d_in[18];

    float* out_recon = (float*)d_out;                   // [N, G]
    float* out_Z     = (float*)d_out + (size_t)NN * GG; // [N, H2]

    float* Hpre; cudaGetSymbolAddress((void**)&Hpre, g_Hpre);
    __nv_bfloat16* Ahi; cudaGetSymbolAddress((void**)&Ahi, g_Ahi);
    __nv_bfloat16* Alo; cudaGetSymbolAddress((void**)&Alo, g_Alo);

    const int SM12864 = 2 * (2 * 128 * 80 + 2 * 64 * 80); // 61440
    const int SM6464  = 2 * (2 * 64 * 80 + 2 * 64 * 80);  // 40960
    cudaFuncSetAttribute((const void*)gemm_hmma<128, 64>,
                         cudaFuncAttributeMaxDynamicSharedMemorySize, SM12864);
    cudaFuncSetAttribute((const void*)gemm_hmma<64, 64>,
                         cudaFuncAttributeMaxDynamicSharedMemorySize, SM6464);

    // 1. dense adj -> per-row column lists
    build_csr<<<NN, 256>>>(adj);

    // 2. encoder GAT layer 1
    cvt_node<<<NN * GG / 4 / 256, 256>>>((const float4*)node);
    pack_headsB<<<(HH1 * GG + 255) / 256, 256>>>(enc1_W, GG, GG);
    gemm_hmma<128, 64><<<dim3(HH1 / 64, NN / 128), 256, SM12864>>>(
        Ahi, Alo, enc1_b, Hpre, GG, HH1);
    feats<<<NN, 128>>>(Hpre, enc1_v0, enc1_v1);
    gat_agg2<<<NN, 128>>>(Hpre);   // -> g_Ahi/g_Alo [4096,512]

    // 3. Z = Hagg @ enc2_W + b (straight to output tail)
    pack_tB<<<(HH1 * HH2 + 255) / 256, 256>>>(enc2_W, HH1, HH2);
    gemm_hmma<64, 64><<<dim3(1, NN / 64), 256, SM6464>>>(
        Ahi, Alo, enc2_b, out_Z, HH1, HH2);

    // 4. decoder GAT layer (K padded 80 -> 128)
    build_hd<<<NN, 128>>>(out_Z, slice, emb);   // -> g_Ahi/g_Alo [4096,128]
    pack_headsB<<<(HH1 * KP_DEC + 255) / 256, 256>>>(dec1_W, HH2 + SEDIM, KP_DEC);
    gemm_hmma<128, 64><<<dim3(HH1 / 64, NN / 128), 256, SM12864>>>(
        Ahi, Alo, dec1_b, Hpre, KP_DEC, HH1);
    feats<<<NN, 128>>>(Hpre, dec1_v0, dec1_v1);
    gat_agg2<<<NN, 128>>>(Hpre);   // -> g_Ahi/g_Alo [4096,512]

    // 5. recon = Hagg @ dec2_W + b
    pack_tB<<<(HH1 * GG + 255) / 256, 256>>>(dec2_W, HH1, GG);
    gemm_hmma<128, 64><<<dim3(GG / 64, NN / 128), 256, SM12864>>>(
        Ahi, Alo, dec2_b, out_recon, HH1, GG);
}

// round 6
// speedup vs baseline: 1.5163x; 1.0269x over previous
#include <cuda_runtime.h>
#include <cuda_bf16.h>
#include <math.h>
#include <stdint.h>

#define NN 4096
#define GG 1024
#define HH1 512
#define HH2 64
#define NHEAD 4
#define CHAN 128
#define SEDIM 16
#define CAP 256
#define KP_DEC 128

// ---------------- scratch (static device globals; no allocation) ----------
__device__ __nv_bfloat16 g_Ahi[NN * GG];   // activation hi (bf16 split)
__device__ __nv_bfloat16 g_Alo[NN * GG];   // activation lo
__device__ __nv_bfloat16 g_Bhi[GG * HH1];  // weight hi, [n][k] K-major
__device__ __nv_bfloat16 g_Blo[GG * HH1];
__device__ float g_Hpre[NN * HH1];
__device__ float g_f1[NHEAD * NN];
__device__ float g_f2[NHEAD * NN];
__device__ int   g_cols[NN * CAP];
__device__ int   g_cnt[NN];

// ---------------- helpers ---------------------------------------------------
__device__ __forceinline__ void bsplit(float x, __nv_bfloat16* h, __nv_bfloat16* l) {
    __nv_bfloat16 hh = __float2bfloat16_rn(x);
    *h = hh;
    *l = __float2bfloat16_rn(x - __bfloat162float(hh));
}
__device__ __forceinline__ uint32_t smem_u32(const void* p) {
    uint32_t a;
    asm("{ .reg .u64 t; cvta.to.shared.u64 t, %1; cvt.u32.u64 %0, t; }" : "=r"(a) : "l"(p));
    return a;
}
#define LDM4(r, addr) \
    asm volatile("ldmatrix.sync.aligned.m8n8.x4.shared.b16 {%0,%1,%2,%3}, [%4];" \
                 : "=r"((r)[0]), "=r"((r)[1]), "=r"((r)[2]), "=r"((r)[3]) : "r"(addr))
#define MMA16816(d, a, b0_, b1_) \
    asm volatile("mma.sync.aligned.m16n8k16.row.col.f32.bf16.bf16.f32 " \
                 "{%0,%1,%2,%3}, {%4,%5,%6,%7}, {%8,%9}, {%0,%1,%2,%3};" \
                 : "+f"((d)[0]), "+f"((d)[1]), "+f"((d)[2]), "+f"((d)[3]) \
                 : "r"((a)[0]), "r"((a)[1]), "r"((a)[2]), "r"((a)[3]), "r"(b0_), "r"(b1_))
#define CP16(dst, src) \
    asm volatile("cp.async.cg.shared.global [%0], [%1], 16;" :: "r"(dst), "l"(src))

// ---------------- CSR build from dense adjacency ---------------------------
__global__ void build_csr(const float* __restrict__ adj) {
    int row = blockIdx.x;
    __shared__ int cnt;
    if (threadIdx.x == 0) cnt = 0;
    __syncthreads();
    const float4* arow = (const float4*)(adj + (size_t)row * NN);
    for (int j4 = threadIdx.x; j4 < NN / 4; j4 += blockDim.x) {
        float4 v = arow[j4];
        if (v.x != 0.f) { int k = atomicAdd(&cnt, 1); if (k < CAP) g_cols[row * CAP + k] = j4 * 4 + 0; }
        if (v.y != 0.f) { int k = atomicAdd(&cnt, 1); if (k < CAP) g_cols[row * CAP + k] = j4 * 4 + 1; }
        if (v.z != 0.f) { int k = atomicAdd(&cnt, 1); if (k < CAP) g_cols[row * CAP + k] = j4 * 4 + 2; }
        if (v.w != 0.f) { int k = atomicAdd(&cnt, 1); if (k < CAP) g_cols[row * CAP + k] = j4 * 4 + 3; }
    }
    __syncthreads();
    if (threadIdx.x == 0) g_cnt[row] = min(cnt, CAP);
}

// ---------------- split node feats into bf16 hi/lo --------------------------
__global__ void cvt_node(const float4* __restrict__ x) {
    int i = blockIdx.x * blockDim.x + threadIdx.x;  // over NN*GG/4
    float4 v = x[i];
    int b = i * 4;
    bsplit(v.x, &g_Ahi[b + 0], &g_Alo[b + 0]);
    bsplit(v.y, &g_Ahi[b + 1], &g_Alo[b + 1]);
    bsplit(v.z, &g_Ahi[b + 2], &g_Alo[b + 2]);
    bsplit(v.w, &g_Ahi[b + 3], &g_Alo[b + 3]);
}

// ---------------- pack [NH,K,CH] head weights -> B[n=512][KPad] + split -----
__global__ void pack_headsB(const float* __restrict__ W, int K, int KPad) {
    int idx = blockIdx.x * blockDim.x + threadIdx.x;
    if (idx >= HH1 * KPad) return;
    int n = idx / KPad, k = idx - n * KPad;
    int h = n >> 7, c = n & 127;
    float v = (k < K) ? W[((size_t)h * K + k) * CHAN + c] : 0.f;
    bsplit(v, &g_Bhi[idx], &g_Blo[idx]);
}

// ---------------- transpose W[K,Nc] -> B[Nc][K] + split ---------------------
__global__ void pack_tB(const float* __restrict__ W, int K, int Nc) {
    int idx = blockIdx.x * blockDim.x + threadIdx.x;
    if (idx >= K * Nc) return;
    int k = idx / Nc, n = idx - k * Nc;
    bsplit(W[idx], &g_Bhi[(size_t)n * K + k], &g_Blo[(size_t)n * K + k]);
}

// ---------------- HMMA bf16-split GEMM, MTILE x NT tiles --------------------
// Round-3 proven LDSM/MMA schedule; cp.async replaces reg-staged loads.
template <int MTILE, int NT>
__global__ void __launch_bounds__(256, 2)
gemm_hmma(const __nv_bfloat16* __restrict__ Ah, const __nv_bfloat16* __restrict__ Al,
          const float* __restrict__ bias, float* __restrict__ C, int K, int Nc) {
    constexpr int WMW = (MTILE == 128) ? 2 : 4;
    constexpr int WNW = 8 / WMW;
    constexpr int WM  = MTILE / WMW;
    constexpr int WN  = NT / WNW;
    constexpr int MT  = WM / 16;
    constexpr int NTL = WN / 8;
    constexpr int NP  = NTL / 2;
    constexpr int ASZ = MTILE * 80;
    constexpr int BSZ = NT * 80;
    constexpr int STG = 2 * ASZ + 2 * BSZ;
    constexpr int AJ  = MTILE / 64;
    constexpr int BJ  = (NT >= 64) ? NT / 64 : 1;

    extern __shared__ char sm[];
    const int tid = threadIdx.x, lane = tid & 31, wid = tid >> 5;
    const int m0 = blockIdx.y * MTILE, n0 = blockIdx.x * NT;
    const int wm0 = (wid % WMW) * WM, wn0 = (wid / WMW) * WN;

    const int ar = (AJ == 2) ? (tid >> 1) : (tid >> 2);
    const int ac = (AJ == 2) ? ((tid & 1) * 16) : ((tid & 3) * 8);
    const size_t abase = (size_t)(m0 + ar) * K + ac;
    const int br = (BJ == 2) ? (tid >> 1) : (tid >> 2);
    const int bc = (BJ == 2) ? ((tid & 1) * 16) : ((tid & 3) * 8);
    const size_t bbase = (size_t)(n0 + br) * K + bc;

    const uint32_t sA = smem_u32(sm);
    const uint32_t stA = ar * 80 + ac * 2;
    const uint32_t stB = br * 80 + bc * 2;

    const int lr = lane & 15, lk = (lane >> 4) * 8;
    const uint32_t aoff = (wm0 + lr) * 80 + lk * 2;
    const uint32_t boff = (wn0 + lr) * 80 + lk * 2;

    float acc[MT][NTL][4];
#pragma unroll
    for (int i = 0; i < MT; i++)
#pragma unroll
        for (int j = 0; j < NTL; j++)
#pragma unroll
            for (int q = 0; q < 4; q++) acc[i][j][q] = 0.f;

    const int NC = K >> 5;

#define GLOADC(c0, buf)                                                        \
    {                                                                          \
        int k0 = (c0) * 32;                                                    \
        uint32_t d = sA + (buf) * STG;                                         \
        _Pragma("unroll") for (int j = 0; j < AJ; j++) {                       \
            CP16(d + stA + j * 16, Ah + abase + k0 + j * 8);                   \
            CP16(d + ASZ + stA + j * 16, Al + abase + k0 + j * 8);             \
        }                                                                      \
        _Pragma("unroll") for (int j = 0; j < BJ; j++) {                       \
            CP16(d + 2 * ASZ + stB + j * 16, g_Bhi + bbase + k0 + j * 8);      \
            CP16(d + 2 * ASZ + BSZ + stB + j * 16, g_Blo + bbase + k0 + j * 8);\
        }                                                                      \
        asm volatile("cp.async.commit_group;" ::: "memory");                   \
    }

    GLOADC(0, 0);
    for (int c = 0; c < NC; c++) {
        if (c + 1 < NC) {
            GLOADC(c + 1, (c + 1) & 1);
            asm volatile("cp.async.wait_group 1;" ::: "memory");
        } else {
            asm volatile("cp.async.wait_group 0;" ::: "memory");
        }
        __syncthreads();
        uint32_t uAh = sA + (c & 1) * STG;
        uint32_t uAl = uAh + ASZ;
        uint32_t uBh = uAh + 2 * ASZ;
        uint32_t uBl = uBh + BSZ;
#pragma unroll
        for (int ks = 0; ks < 2; ks++) {
            uint32_t ah[MT][4], al[MT][4], bh[NP][4], bl[NP][4];
#pragma unroll
            for (int mt = 0; mt < MT; mt++) LDM4(ah[mt], uAh + aoff + mt * 1280 + ks * 32);
#pragma unroll
            for (int mt = 0; mt < MT; mt++) LDM4(al[mt], uAl + aoff + mt * 1280 + ks * 32);
#pragma unroll
            for (int p = 0; p < NP; p++) LDM4(bh[p], uBh + boff + p * 1280 + ks * 32);
#pragma unroll
            for (int p = 0; p < NP; p++) LDM4(bl[p], uBl + boff + p * 1280 + ks * 32);
            // term 1: hi*hi
#pragma unroll
            for (int mt = 0; mt < MT; mt++)
#pragma unroll
                for (int p = 0; p < NP; p++) {
                    MMA16816(acc[mt][2 * p],     ah[mt], bh[p][0], bh[p][2]);
                    MMA16816(acc[mt][2 * p + 1], ah[mt], bh[p][1], bh[p][3]);
                }
            // term 2: hi*lo
#pragma unroll
            for (int mt = 0; mt < MT; mt++)
#pragma unroll
                for (int p = 0; p < NP; p++) {
                    MMA16816(acc[mt][2 * p],     ah[mt], bl[p][0], bl[p][2]);
                    MMA16816(acc[mt][2 * p + 1], ah[mt], bl[p][1], bl[p][3]);
                }
            // term 3: lo*hi
#pragma unroll
            for (int mt = 0; mt < MT; mt++)
#pragma unroll
                for (int p = 0; p < NP; p++) {
                    MMA16816(acc[mt][2 * p],     al[mt], bh[p][0], bh[p][2]);
                    MMA16816(acc[mt][2 * p + 1], al[mt], bh[p][1], bh[p][3]);
                }
        }
        __syncthreads();
    }
#undef GLOADC

    // epilogue: bias + store
    int g = lane >> 2, tg = lane & 3;
#pragma unroll
    for (int mt = 0; mt < MT; mt++) {
        int row = m0 + wm0 + mt * 16 + g;
#pragma unroll
        for (int nt = 0; nt < NTL; nt++) {
            int col = n0 + wn0 + nt * 8 + tg * 2;
            float b0 = bias[col], b1 = bias[col + 1];
            C[(size_t)row * Nc + col]           = acc[mt][nt][0] + b0;
            C[(size_t)row * Nc + col + 1]       = acc[mt][nt][1] + b1;
            C[(size_t)(row + 8) * Nc + col]     = acc[mt][nt][2] + b0;
            C[(size_t)(row + 8) * Nc + col + 1] = acc[mt][nt][3] + b1;
        }
    }
}

// ---------------- attention features f1 = h@v0, f2 = h@v1 ------------------
// block = 512 threads = 16 warps = 4 rows x 4 heads
__global__ void __launch_bounds__(512) feats2(const float* __restrict__ Hpre,
                                              const float* __restrict__ v0,
                                              const float* __restrict__ v1) {
    int tid = threadIdx.x, wid = tid >> 5, lid = tid & 31;
    int n = blockIdx.x * 4 + (wid >> 2);
    int h = wid & 3;
    float4 hv = *(const float4*)(Hpre + (size_t)n * HH1 + h * CHAN + lid * 4);
    float4 a  = *(const float4*)(v0 + h * CHAN + lid * 4);
    float4 b  = *(const float4*)(v1 + h * CHAN + lid * 4);
    float s1 = hv.x * a.x + hv.y * a.y + hv.z * a.z + hv.w * a.w;
    float s2 = hv.x * b.x + hv.y * b.y + hv.z * b.z + hv.w * b.w;
#pragma unroll
    for (int o = 16; o > 0; o >>= 1) {
        s1 += __shfl_down_sync(0xffffffffu, s1, o);
        s2 += __shfl_down_sync(0xffffffffu, s2, o);
    }
    if (lid == 0) {
        g_f1[h * NN + n] = s1;
        g_f2[h * NN + n] = s2;
    }
}

// ---------------- sparse attention softmax + aggregation + ELU -------------
// warp = one (row, head); register softmax, no smem, no block syncs
__global__ void __launch_bounds__(128) gat_agg3(const float* __restrict__ Hpre) {
    int row = blockIdx.x, tid = threadIdx.x, wid = tid >> 5, lid = tid & 31;
    int cnt = g_cnt[row];
    const int* cols = g_cols + row * CAP;
    const float* f2h = g_f2 + wid * NN;
    float f1r = g_f1[wid * NN + row];
    const float* Hb = Hpre + wid * CHAN + lid * 4;
    float4 acc = {0.f, 0.f, 0.f, 0.f};
    float inv;

    if (cnt <= 32) {
        bool valid = lid < cnt;
        int col = valid ? cols[lid] : 0;
        float u = 0.f;
        if (valid) {
            float x = f1r + f2h[col];
            u = 1.f / (1.f + expf(-x)) - 0.5f;
        }
        float mv = (valid && u != 0.f) ? u : -1e30f;
#pragma unroll
        for (int o = 16; o; o >>= 1) mv = fmaxf(mv, __shfl_xor_sync(0xffffffffu, mv, o));
        float e = (valid && u != 0.f) ? expf(u - mv) : 0.f;
        float s = e;
#pragma unroll
        for (int o = 16; o; o >>= 1) s += __shfl_xor_sync(0xffffffffu, s, o);
        inv = 1.f / fmaxf(s, 1e-30f);
        for (int k = 0; k < cnt; k++) {
            float w = __shfl_sync(0xffffffffu, e, k);
            int c2 = __shfl_sync(0xffffffffu, col, k);
            if (w != 0.f) {
                float4 hv = *(const float4*)(Hb + (size_t)c2 * HH1);
                acc.x += w * hv.x; acc.y += w * hv.y;
                acc.z += w * hv.z; acc.w += w * hv.w;
            }
        }
    } else {
        // general path (rare): 3 passes with recompute
        float mv = -1e30f;
        for (int c0 = 0; c0 < cnt; c0 += 32) {
            int k = c0 + lid;
            if (k < cnt) {
                float x = f1r + f2h[cols[k]];
                float u = 1.f / (1.f + expf(-x)) - 0.5f;
                if (u != 0.f) mv = fmaxf(mv, u);
            }
        }
#pragma unroll
        for (int o = 16; o; o >>= 1) mv = fmaxf(mv, __shfl_xor_sync(0xffffffffu, mv, o));
        float s = 0.f;
        for (int c0 = 0; c0 < cnt; c0 += 32) {
            int k = c0 + lid;
            if (k < cnt) {
                float x = f1r + f2h[cols[k]];
                float u = 1.f / (1.f + expf(-x)) - 0.5f;
                if (u != 0.f) s += expf(u - mv);
            }
        }
#pragma unroll
        for (int o = 16; o; o >>= 1) s += __shfl_xor_sync(0xffffffffu, s, o);
        inv = 1.f / fmaxf(s, 1e-30f);
        for (int c0 = 0; c0 < cnt; c0 += 32) {
            int k = c0 + lid;
            int col = (k < cnt) ? cols[k] : 0;
            float e = 0.f;
            if (k < cnt) {
                float x = f1r + f2h[col];
                float u = 1.f / (1.f + expf(-x)) - 0.5f;
                if (u != 0.f) e = expf(u - mv);
            }
            int lim = min(32, cnt - c0);
            for (int j = 0; j < lim; j++) {
                float w = __shfl_sync(0xffffffffu, e, j);
                int c2 = __shfl_sync(0xffffffffu, col, j);
                if (w != 0.f) {
                    float4 hv = *(const float4*)(Hb + (size_t)c2 * HH1);
                    acc.x += w * hv.x; acc.y += w * hv.y;
                    acc.z += w * hv.z; acc.w += w * hv.w;
                }
            }
        }
    }

    acc.x *= inv; acc.y *= inv; acc.z *= inv; acc.w *= inv;
    acc.x = (acc.x > 0.f) ? acc.x : expm1f(acc.x);
    acc.y = (acc.y > 0.f) ? acc.y : expm1f(acc.y);
    acc.z = (acc.z > 0.f) ? acc.z : expm1f(acc.z);
    acc.w = (acc.w > 0.f) ? acc.w : expm1f(acc.w);
    size_t base = (size_t)row * HH1 + wid * CHAN + lid * 4;
    bsplit(acc.x, &g_Ahi[base + 0], &g_Alo[base + 0]);
    bsplit(acc.y, &g_Ahi[base + 1], &g_Alo[base + 1]);
    bsplit(acc.z, &g_Ahi[base + 2], &g_Alo[base + 2]);
    bsplit(acc.w, &g_Ahi[base + 3], &g_Alo[base + 3]);
}

// ---------------- Hd = concat(Z, emb[slice], zero-pad to 128), split -------
__global__ void build_hd(const float* __restrict__ Z,
                         const int* __restrict__ slice,
                         const float* __restrict__ emb) {
    int n = blockIdx.x, t = threadIdx.x;  // 128 threads
    float v = 0.f;
    if (t < HH2) v = Z[(size_t)n * HH2 + t];
    else if (t < HH2 + SEDIM) v = emb[slice[n] * SEDIM + (t - HH2)];
    bsplit(v, &g_Ahi[(size_t)n * KP_DEC + t], &g_Alo[(size_t)n * KP_DEC + t]);
}

extern "C" void kernel_launch(void* const* d_in, const int* in_sizes, int n_in,
                              void* d_out, int out_size) {
    const float* adj     = (const float*)d_in[0];
    const float* node    = (const float*)d_in[1];
    const int*   slice   = (const int*)d_in[4];
    const float* enc1_W  = (const float*)d_in[6];
    const float* enc1_b  = (const float*)d_in[7];
    const float* enc1_v0 = (const float*)d_in[8];
    const float* enc1_v1 = (const float*)d_in[9];
    const float* enc2_W  = (const float*)d_in[10];
    const float* enc2_b  = (const float*)d_in[11];
    const float* dec1_W  = (const float*)d_in[12];
    const float* dec1_b  = (const float*)d_in[13];
    const float* dec1_v0 = (const float*)d_in[14];
    const float* dec1_v1 = (const float*)d_in[15];
    const float* dec2_W  = (const float*)d_in[16];
    const float* dec2_b  = (const float*)d_in[17];
    const float* emb     = (const float*)d_in[18];

    float* out_recon = (float*)d_out;                   // [N, G]
    float* out_Z     = (float*)d_out + (size_t)NN * GG; // [N, H2]

    float* Hpre; cudaGetSymbolAddress((void**)&Hpre, g_Hpre);
    __nv_bfloat16* Ahi; cudaGetSymbolAddress((void**)&Ahi, g_Ahi);
    __nv_bfloat16* Alo; cudaGetSymbolAddress((void**)&Alo, g_Alo);

    const int SM128 = 2 * (2 * 128 * 80 + 2 * 128 * 80); // 81920
    const int SM64  = 2 * (2 * 64 * 80 + 2 * 64 * 80);   // 40960
    cudaFuncSetAttribute((const void*)gemm_hmma<128, 128>,
                         cudaFuncAttributeMaxDynamicSharedMemorySize, SM128);
    cudaFuncSetAttribute((const void*)gemm_hmma<64, 64>,
                         cudaFuncAttributeMaxDynamicSharedMemorySize, SM64);

    // 1. dense adj -> per-row column lists
    build_csr<<<NN, 256>>>(adj);

    // 2. encoder GAT layer 1
    cvt_node<<<NN * GG / 4 / 256, 256>>>((const float4*)node);
    pack_headsB<<<(HH1 * GG + 255) / 256, 256>>>(enc1_W, GG, GG);
    gemm_hmma<128, 128><<<dim3(HH1 / 128, NN / 128), 256, SM128>>>(
        Ahi, Alo, enc1_b, Hpre, GG, HH1);
    feats2<<<NN / 4, 512>>>(Hpre, enc1_v0, enc1_v1);
    gat_agg3<<<NN, 128>>>(Hpre);   // -> g_Ahi/g_Alo [4096,512]

    // 3. Z = Hagg @ enc2_W + b (straight to output tail)
    pack_tB<<<(HH1 * HH2 + 255) / 256, 256>>>(enc2_W, HH1, HH2);
    gemm_hmma<64, 64><<<dim3(1, NN / 64), 256, SM64>>>(
        Ahi, Alo, enc2_b, out_Z, HH1, HH2);

    // 4. decoder GAT layer (K padded 80 -> 128)
    build_hd<<<NN, 128>>>(out_Z, slice, emb);   // -> g_Ahi/g_Alo [4096,128]
    pack_headsB<<<(HH1 * KP_DEC + 255) / 256, 256>>>(dec1_W, HH2 + SEDIM, KP_DEC);
    gemm_hmma<128, 128><<<dim3(HH1 / 128, NN / 128), 256, SM128>>>(
        Ahi, Alo, dec1_b, Hpre, KP_DEC, HH1);
    feats2<<<NN / 4, 512>>>(Hpre, dec1_v0, dec1_v1);
    gat_agg3<<<NN, 128>>>(Hpre);   // -> g_Ahi/g_Alo [4096,512]

    // 5. recon = Hagg @ dec2_W + b
    pack_tB<<<(HH1 * GG + 255) / 256, 256>>>(dec2_W, HH1, GG);
    gemm_hmma<128, 128><<<dim3(GG / 128, NN / 128), 256, SM128>>>(
        Ahi, Alo, dec2_b, out_recon, HH1, GG);
}

// round 7
// speedup vs baseline: 1.5328x; 1.0109x over previous
#include <cuda_runtime.h>
#include <cuda_bf16.h>
#include <math.h>
#include <stdint.h>

#define NN 4096
#define GG 1024
#define HH1 512
#define HH2 64
#define NHEAD 4
#define CHAN 128
#define SEDIM 16
#define CAP 256
#define KP_DEC 128

// ---------------- scratch (static device globals; no allocation) ----------
__device__ __nv_bfloat16 g_Ahi[NN * GG];   // activation hi (bf16 split)
__device__ __nv_bfloat16 g_Alo[NN * GG];   // activation lo
__device__ __nv_bfloat16 g_Bhi[GG * HH1];  // weight hi, [n][k] K-major
__device__ __nv_bfloat16 g_Blo[GG * HH1];
__device__ float g_Hpre[NN * HH1];
__device__ float g_P0[NN * GG];            // split-K partial sums (16 MB)
__device__ float g_f1[NHEAD * NN];
__device__ float g_f2[NHEAD * NN];
__device__ int   g_cols[NN * CAP];
__device__ int   g_cnt[NN];

// ---------------- helpers ---------------------------------------------------
__device__ __forceinline__ void bsplit(float x, __nv_bfloat16* h, __nv_bfloat16* l) {
    __nv_bfloat16 hh = __float2bfloat16_rn(x);
    *h = hh;
    *l = __float2bfloat16_rn(x - __bfloat162float(hh));
}
__device__ __forceinline__ uint32_t smem_u32(const void* p) {
    uint32_t a;
    asm("{ .reg .u64 t; cvta.to.shared.u64 t, %1; cvt.u32.u64 %0, t; }" : "=r"(a) : "l"(p));
    return a;
}
#define LDM4(r, addr) \
    asm volatile("ldmatrix.sync.aligned.m8n8.x4.shared.b16 {%0,%1,%2,%3}, [%4];" \
                 : "=r"((r)[0]), "=r"((r)[1]), "=r"((r)[2]), "=r"((r)[3]) : "r"(addr))
#define MMA16816(d, a, b0_, b1_) \
    asm volatile("mma.sync.aligned.m16n8k16.row.col.f32.bf16.bf16.f32 " \
                 "{%0,%1,%2,%3}, {%4,%5,%6,%7}, {%8,%9}, {%0,%1,%2,%3};" \
                 : "+f"((d)[0]), "+f"((d)[1]), "+f"((d)[2]), "+f"((d)[3]) \
                 : "r"((a)[0]), "r"((a)[1]), "r"((a)[2]), "r"((a)[3]), "r"(b0_), "r"(b1_))
#define CP16(dst, src) \
    asm volatile("cp.async.cg.shared.global [%0], [%1], 16;" :: "r"(dst), "l"(src))

// ---------------- CSR build from dense adjacency ---------------------------
__global__ void build_csr(const float* __restrict__ adj) {
    int row = blockIdx.x;
    __shared__ int cnt;
    if (threadIdx.x == 0) cnt = 0;
    __syncthreads();
    const float4* arow = (const float4*)(adj + (size_t)row * NN);
    for (int j4 = threadIdx.x; j4 < NN / 4; j4 += blockDim.x) {
        float4 v = arow[j4];
        if (v.x != 0.f) { int k = atomicAdd(&cnt, 1); if (k < CAP) g_cols[row * CAP + k] = j4 * 4 + 0; }
        if (v.y != 0.f) { int k = atomicAdd(&cnt, 1); if (k < CAP) g_cols[row * CAP + k] = j4 * 4 + 1; }
        if (v.z != 0.f) { int k = atomicAdd(&cnt, 1); if (k < CAP) g_cols[row * CAP + k] = j4 * 4 + 2; }
        if (v.w != 0.f) { int k = atomicAdd(&cnt, 1); if (k < CAP) g_cols[row * CAP + k] = j4 * 4 + 3; }
    }
    __syncthreads();
    if (threadIdx.x == 0) g_cnt[row] = min(cnt, CAP);
}

// ---------------- split node feats into bf16 hi/lo --------------------------
__global__ void cvt_node(const float4* __restrict__ x) {
    int i = blockIdx.x * blockDim.x + threadIdx.x;  // over NN*GG/4
    float4 v = x[i];
    int b = i * 4;
    bsplit(v.x, &g_Ahi[b + 0], &g_Alo[b + 0]);
    bsplit(v.y, &g_Ahi[b + 1], &g_Alo[b + 1]);
    bsplit(v.z, &g_Ahi[b + 2], &g_Alo[b + 2]);
    bsplit(v.w, &g_Ahi[b + 3], &g_Alo[b + 3]);
}

// ---------------- pack [NH,K,CH] head weights -> B[n=512][KPad] + split -----
__global__ void pack_headsB(const float* __restrict__ W, int K, int KPad) {
    int idx = blockIdx.x * blockDim.x + threadIdx.x;
    if (idx >= HH1 * KPad) return;
    int n = idx / KPad, k = idx - n * KPad;
    int h = n >> 7, c = n & 127;
    float v = (k < K) ? W[((size_t)h * K + k) * CHAN + c] : 0.f;
    bsplit(v, &g_Bhi[idx], &g_Blo[idx]);
}

// ---------------- transpose W[K,Nc] -> B[Nc][K] + split ---------------------
__global__ void pack_tB(const float* __restrict__ W, int K, int Nc) {
    int idx = blockIdx.x * blockDim.x + threadIdx.x;
    if (idx >= K * Nc) return;
    int k = idx / Nc, n = idx - k * Nc;
    bsplit(W[idx], &g_Bhi[(size_t)n * K + k], &g_Blo[(size_t)n * K + k]);
}

// ---------------- split-K partial reduce + bias ----------------------------
// out[e] = sum_s P[e + s*NN*Nc] + bias[e % Nc].  Nc power of 2, /4 aligned.
__global__ void reduceP(const float4* __restrict__ P, float4* __restrict__ out,
                        const float4* __restrict__ bias, int NcDiv4, int nsplit,
                        int total4) {
    int idx = blockIdx.x * blockDim.x + threadIdx.x;
    if (idx >= total4) return;
    float4 s = P[idx];
    int stride4 = total4;
    for (int k = 1; k < nsplit; k++) {
        float4 q = P[idx + k * stride4];
        s.x += q.x; s.y += q.y; s.z += q.z; s.w += q.w;
    }
    float4 b = bias[idx & (NcDiv4 - 1)];
    s.x += b.x; s.y += b.y; s.z += b.z; s.w += b.w;
    out[idx] = s;
}

// ---------------- HMMA bf16-split GEMM, MTILE x NT tiles --------------------
// Round-3 proven LDSM/MMA schedule; cp.async staging; optional split-K via
// blockIdx.z (bias==null -> raw partial written at C + z*NN*Nc).
template <int MTILE, int NT>
__global__ void __launch_bounds__(256, 2)
gemm_hmma(const __nv_bfloat16* __restrict__ Ah, const __nv_bfloat16* __restrict__ Al,
          const float* __restrict__ bias, float* __restrict__ C,
          int Kfull, int Ksplit, int Nc) {
    constexpr int WMW = (MTILE == 128) ? 2 : 4;
    constexpr int WNW = 8 / WMW;
    constexpr int WM  = MTILE / WMW;
    constexpr int WN  = NT / WNW;
    constexpr int MT  = WM / 16;
    constexpr int NTL = WN / 8;
    constexpr int NP  = NTL / 2;
    constexpr int ASZ = MTILE * 80;
    constexpr int BSZ = NT * 80;
    constexpr int STG = 2 * ASZ + 2 * BSZ;
    constexpr int AJ  = MTILE / 64;
    constexpr int BJ  = (NT >= 64) ? NT / 64 : 1;

    extern __shared__ char sm[];
    const int tid = threadIdx.x, lane = tid & 31, wid = tid >> 5;
    const int m0 = blockIdx.y * MTILE, n0 = blockIdx.x * NT;
    const int koff = blockIdx.z * Ksplit;
    const int wm0 = (wid % WMW) * WM, wn0 = (wid / WMW) * WN;

    const int ar = (AJ == 2) ? (tid >> 1) : (tid >> 2);
    const int ac = (AJ == 2) ? ((tid & 1) * 16) : ((tid & 3) * 8);
    const size_t abase = (size_t)(m0 + ar) * Kfull + koff + ac;
    const int br = (BJ == 2) ? (tid >> 1) : (tid >> 2);
    const int bc = (BJ == 2) ? ((tid & 1) * 16) : ((tid & 3) * 8);
    const size_t bbase = (size_t)(n0 + br) * Kfull + koff + bc;

    const uint32_t sA = smem_u32(sm);
    const uint32_t stA = ar * 80 + ac * 2;
    const uint32_t stB = br * 80 + bc * 2;

    const int lr = lane & 15, lk = (lane >> 4) * 8;
    const uint32_t aoff = (wm0 + lr) * 80 + lk * 2;
    const uint32_t boff = (wn0 + lr) * 80 + lk * 2;

    float acc[MT][NTL][4];
#pragma unroll
    for (int i = 0; i < MT; i++)
#pragma unroll
        for (int j = 0; j < NTL; j++)
#pragma unroll
            for (int q = 0; q < 4; q++) acc[i][j][q] = 0.f;

    const int NC = Ksplit >> 5;

#define GLOADC(c0, buf)                                                        \
    {                                                                          \
        int k0 = (c0) * 32;                                                    \
        uint32_t d = sA + (buf) * STG;                                         \
        _Pragma("unroll") for (int j = 0; j < AJ; j++) {                       \
            CP16(d + stA + j * 16, Ah + abase + k0 + j * 8);                   \
            CP16(d + ASZ + stA + j * 16, Al + abase + k0 + j * 8);             \
        }                                                                      \
        _Pragma("unroll") for (int j = 0; j < BJ; j++) {                       \
            CP16(d + 2 * ASZ + stB + j * 16, g_Bhi + bbase + k0 + j * 8);      \
            CP16(d + 2 * ASZ + BSZ + stB + j * 16, g_Blo + bbase + k0 + j * 8);\
        }                                                                      \
        asm volatile("cp.async.commit_group;" ::: "memory");                   \
    }

    GLOADC(0, 0);
    for (int c = 0; c < NC; c++) {
        if (c + 1 < NC) {
            GLOADC(c + 1, (c + 1) & 1);
            asm volatile("cp.async.wait_group 1;" ::: "memory");
        } else {
            asm volatile("cp.async.wait_group 0;" ::: "memory");
        }
        __syncthreads();
        uint32_t uAh = sA + (c & 1) * STG;
        uint32_t uAl = uAh + ASZ;
        uint32_t uBh = uAh + 2 * ASZ;
        uint32_t uBl = uBh + BSZ;
#pragma unroll
        for (int ks = 0; ks < 2; ks++) {
            uint32_t ah[MT][4], al[MT][4], bh[NP][4], bl[NP][4];
#pragma unroll
            for (int mt = 0; mt < MT; mt++) LDM4(ah[mt], uAh + aoff + mt * 1280 + ks * 32);
#pragma unroll
            for (int mt = 0; mt < MT; mt++) LDM4(al[mt], uAl + aoff + mt * 1280 + ks * 32);
#pragma unroll
            for (int p = 0; p < NP; p++) LDM4(bh[p], uBh + boff + p * 1280 + ks * 32);
#pragma unroll
            for (int p = 0; p < NP; p++) LDM4(bl[p], uBl + boff + p * 1280 + ks * 32);
            // term 1: hi*hi
#pragma unroll
            for (int mt = 0; mt < MT; mt++)
#pragma unroll
                for (int p = 0; p < NP; p++) {
                    MMA16816(acc[mt][2 * p],     ah[mt], bh[p][0], bh[p][2]);
                    MMA16816(acc[mt][2 * p + 1], ah[mt], bh[p][1], bh[p][3]);
                }
            // term 2: hi*lo
#pragma unroll
            for (int mt = 0; mt < MT; mt++)
#pragma unroll
                for (int p = 0; p < NP; p++) {
                    MMA16816(acc[mt][2 * p],     ah[mt], bl[p][0], bl[p][2]);
                    MMA16816(acc[mt][2 * p + 1], ah[mt], bl[p][1], bl[p][3]);
                }
            // term 3: lo*hi
#pragma unroll
            for (int mt = 0; mt < MT; mt++)
#pragma unroll
                for (int p = 0; p < NP; p++) {
                    MMA16816(acc[mt][2 * p],     al[mt], bh[p][0], bh[p][2]);
                    MMA16816(acc[mt][2 * p + 1], al[mt], bh[p][1], bh[p][3]);
                }
        }
        __syncthreads();
    }
#undef GLOADC

    // epilogue
    float* Cz = C + (size_t)blockIdx.z * NN * Nc;
    int g = lane >> 2, tg = lane & 3;
#pragma unroll
    for (int mt = 0; mt < MT; mt++) {
        int row = m0 + wm0 + mt * 16 + g;
#pragma unroll
        for (int nt = 0; nt < NTL; nt++) {
            int col = n0 + wn0 + nt * 8 + tg * 2;
            float b0 = bias ? bias[col] : 0.f, b1 = bias ? bias[col + 1] : 0.f;
            Cz[(size_t)row * Nc + col]           = acc[mt][nt][0] + b0;
            Cz[(size_t)row * Nc + col + 1]       = acc[mt][nt][1] + b1;
            Cz[(size_t)(row + 8) * Nc + col]     = acc[mt][nt][2] + b0;
            Cz[(size_t)(row + 8) * Nc + col + 1] = acc[mt][nt][3] + b1;
        }
    }
}

// ---------------- attention features f1 = h@v0, f2 = h@v1 ------------------
// block = 512 threads = 16 warps = 4 rows x 4 heads
__global__ void __launch_bounds__(512) feats2(const float* __restrict__ Hpre,
                                              const float* __restrict__ v0,
                                              const float* __restrict__ v1) {
    int tid = threadIdx.x, wid = tid >> 5, lid = tid & 31;
    int n = blockIdx.x * 4 + (wid >> 2);
    int h = wid & 3;
    float4 hv = *(const float4*)(Hpre + (size_t)n * HH1 + h * CHAN + lid * 4);
    float4 a  = *(const float4*)(v0 + h * CHAN + lid * 4);
    float4 b  = *(const float4*)(v1 + h * CHAN + lid * 4);
    float s1 = hv.x * a.x + hv.y * a.y + hv.z * a.z + hv.w * a.w;
    float s2 = hv.x * b.x + hv.y * b.y + hv.z * b.z + hv.w * b.w;
#pragma unroll
    for (int o = 16; o > 0; o >>= 1) {
        s1 += __shfl_down_sync(0xffffffffu, s1, o);
        s2 += __shfl_down_sync(0xffffffffu, s2, o);
    }
    if (lid == 0) {
        g_f1[h * NN + n] = s1;
        g_f2[h * NN + n] = s2;
    }
}

// ---------------- sparse attention softmax + aggregation + ELU -------------
// warp = one (row, head); register softmax, no smem, no block syncs
__global__ void __launch_bounds__(128) gat_agg3(const float* __restrict__ Hpre) {
    int row = blockIdx.x, tid = threadIdx.x, wid = tid >> 5, lid = tid & 31;
    int cnt = g_cnt[row];
    const int* cols = g_cols + row * CAP;
    const float* f2h = g_f2 + wid * NN;
    float f1r = g_f1[wid * NN + row];
    const float* Hb = Hpre + wid * CHAN + lid * 4;
    float4 acc = {0.f, 0.f, 0.f, 0.f};
    float inv;

    if (cnt <= 32) {
        bool valid = lid < cnt;
        int col = valid ? cols[lid] : 0;
        float u = 0.f;
        if (valid) {
            float x = f1r + f2h[col];
            u = 1.f / (1.f + expf(-x)) - 0.5f;
        }
        float mv = (valid && u != 0.f) ? u : -1e30f;
#pragma unroll
        for (int o = 16; o; o >>= 1) mv = fmaxf(mv, __shfl_xor_sync(0xffffffffu, mv, o));
        float e = (valid && u != 0.f) ? expf(u - mv) : 0.f;
        float s = e;
#pragma unroll
        for (int o = 16; o; o >>= 1) s += __shfl_xor_sync(0xffffffffu, s, o);
        inv = 1.f / fmaxf(s, 1e-30f);
        for (int k = 0; k < cnt; k++) {
            float w = __shfl_sync(0xffffffffu, e, k);
            int c2 = __shfl_sync(0xffffffffu, col, k);
            if (w != 0.f) {
                float4 hv = *(const float4*)(Hb + (size_t)c2 * HH1);
                acc.x += w * hv.x; acc.y += w * hv.y;
                acc.z += w * hv.z; acc.w += w * hv.w;
            }
        }
    } else {
        float mv = -1e30f;
        for (int c0 = 0; c0 < cnt; c0 += 32) {
            int k = c0 + lid;
            if (k < cnt) {
                float x = f1r + f2h[cols[k]];
                float u = 1.f / (1.f + expf(-x)) - 0.5f;
                if (u != 0.f) mv = fmaxf(mv, u);
            }
        }
#pragma unroll
        for (int o = 16; o; o >>= 1) mv = fmaxf(mv, __shfl_xor_sync(0xffffffffu, mv, o));
        float s = 0.f;
        for (int c0 = 0; c0 < cnt; c0 += 32) {
            int k = c0 + lid;
            if (k < cnt) {
                float x = f1r + f2h[cols[k]];
                float u = 1.f / (1.f + expf(-x)) - 0.5f;
                if (u != 0.f) s += expf(u - mv);
            }
        }
#pragma unroll
        for (int o = 16; o; o >>= 1) s += __shfl_xor_sync(0xffffffffu, s, o);
        inv = 1.f / fmaxf(s, 1e-30f);
        for (int c0 = 0; c0 < cnt; c0 += 32) {
            int k = c0 + lid;
            int col = (k < cnt) ? cols[k] : 0;
            float e = 0.f;
            if (k < cnt) {
                float x = f1r + f2h[col];
                float u = 1.f / (1.f + expf(-x)) - 0.5f;
                if (u != 0.f) e = expf(u - mv);
            }
            int lim = min(32, cnt - c0);
            for (int j = 0; j < lim; j++) {
                float w = __shfl_sync(0xffffffffu, e, j);
                int c2 = __shfl_sync(0xffffffffu, col, j);
                if (w != 0.f) {
                    float4 hv = *(const float4*)(Hb + (size_t)c2 * HH1);
                    acc.x += w * hv.x; acc.y += w * hv.y;
                    acc.z += w * hv.z; acc.w += w * hv.w;
                }
            }
        }
    }

    acc.x *= inv; acc.y *= inv; acc.z *= inv; acc.w *= inv;
    acc.x = (acc.x > 0.f) ? acc.x : expm1f(acc.x);
    acc.y = (acc.y > 0.f) ? acc.y : expm1f(acc.y);
    acc.z = (acc.z > 0.f) ? acc.z : expm1f(acc.z);
    acc.w = (acc.w > 0.f) ? acc.w : expm1f(acc.w);
    size_t base = (size_t)row * HH1 + wid * CHAN + lid * 4;
    bsplit(acc.x, &g_Ahi[base + 0], &g_Alo[base + 0]);
    bsplit(acc.y, &g_Ahi[base + 1], &g_Alo[base + 1]);
    bsplit(acc.z, &g_Ahi[base + 2], &g_Alo[base + 2]);
    bsplit(acc.w, &g_Ahi[base + 3], &g_Alo[base + 3]);
}

// ---------------- Hd = concat(Z, emb[slice], zero-pad to 128), split -------
__global__ void build_hd(const float* __restrict__ Z,
                         const int* __restrict__ slice,
                         const float* __restrict__ emb) {
    int n = blockIdx.x, t = threadIdx.x;  // 128 threads
    float v = 0.f;
    if (t < HH2) v = Z[(size_t)n * HH2 + t];
    else if (t < HH2 + SEDIM) v = emb[slice[n] * SEDIM + (t - HH2)];
    bsplit(v, &g_Ahi[(size_t)n * KP_DEC + t], &g_Alo[(size_t)n * KP_DEC + t]);
}

extern "C" void kernel_launch(void* const* d_in, const int* in_sizes, int n_in,
                              void* d_out, int out_size) {
    const float* adj     = (const float*)d_in[0];
    const float* node    = (const float*)d_in[1];
    const int*   slice   = (const int*)d_in[4];
    const float* enc1_W  = (const float*)d_in[6];
    const float* enc1_b  = (const float*)d_in[7];
    const float* enc1_v0 = (const float*)d_in[8];
    const float* enc1_v1 = (const float*)d_in[9];
    const float* enc2_W  = (const float*)d_in[10];
    const float* enc2_b  = (const float*)d_in[11];
    const float* dec1_W  = (const float*)d_in[12];
    const float* dec1_b  = (const float*)d_in[13];
    const float* dec1_v0 = (const float*)d_in[14];
    const float* dec1_v1 = (const float*)d_in[15];
    const float* dec2_W  = (const float*)d_in[16];
    const float* dec2_b  = (const float*)d_in[17];
    const float* emb     = (const float*)d_in[18];

    float* out_recon = (float*)d_out;                   // [N, G]
    float* out_Z     = (float*)d_out + (size_t)NN * GG; // [N, H2]

    float* Hpre; cudaGetSymbolAddress((void**)&Hpre, g_Hpre);
    float* P0;   cudaGetSymbolAddress((void**)&P0, g_P0);
    __nv_bfloat16* Ahi; cudaGetSymbolAddress((void**)&Ahi, g_Ahi);
    __nv_bfloat16* Alo; cudaGetSymbolAddress((void**)&Alo, g_Alo);

    const int SM128 = 2 * (2 * 128 * 80 + 2 * 128 * 80); // 81920
    const int SM64  = 2 * (2 * 64 * 80 + 2 * 64 * 80);   // 40960
    cudaFuncSetAttribute((const void*)gemm_hmma<128, 128>,
                         cudaFuncAttributeMaxDynamicSharedMemorySize, SM128);
    cudaFuncSetAttribute((const void*)gemm_hmma<64, 64>,
                         cudaFuncAttributeMaxDynamicSharedMemorySize, SM64);

    // 1. dense adj -> per-row column lists
    build_csr<<<NN, 256>>>(adj);

    // 2. encoder GAT layer 1 — split-K=2 (256 CTAs, 2/SM) + reduce
    cvt_node<<<NN * GG / 4 / 256, 256>>>((const float4*)node);
    pack_headsB<<<(HH1 * GG + 255) / 256, 256>>>(enc1_W, GG, GG);
    gemm_hmma<128, 128><<<dim3(4, 32, 2), 256, SM128>>>(
        Ahi, Alo, nullptr, P0, GG, GG / 2, HH1);
    reduceP<<<(NN * HH1 / 4 + 255) / 256, 256>>>(
        (const float4*)P0, (float4*)Hpre, (const float4*)enc1_b, HH1 / 4, 2, NN * HH1 / 4);
    feats2<<<NN / 4, 512>>>(Hpre, enc1_v0, enc1_v1);
    gat_agg3<<<NN, 128>>>(Hpre);   // -> g_Ahi/g_Alo [4096,512]

    // 3. Z = Hagg @ enc2_W + b — split-K=4 (256 CTAs) + reduce into out tail
    pack_tB<<<(HH1 * HH2 + 255) / 256, 256>>>(enc2_W, HH1, HH2);
    gemm_hmma<64, 64><<<dim3(1, 64, 4), 256, SM64>>>(
        Ahi, Alo, nullptr, P0, HH1, HH1 / 4, HH2);
    reduceP<<<(NN * HH2 / 4 + 255) / 256, 256>>>(
        (const float4*)P0, (float4*)out_Z, (const float4*)enc2_b, HH2 / 4, 4, NN * HH2 / 4);

    // 4. decoder GAT layer (K padded 80 -> 128; small K, no split)
    build_hd<<<NN, 128>>>(out_Z, slice, emb);   // -> g_Ahi/g_Alo [4096,128]
    pack_headsB<<<(HH1 * KP_DEC + 255) / 256, 256>>>(dec1_W, HH2 + SEDIM, KP_DEC);
    gemm_hmma<128, 128><<<dim3(4, 32, 1), 256, SM128>>>(
        Ahi, Alo, dec1_b, Hpre, KP_DEC, KP_DEC, HH1);
    feats2<<<NN / 4, 512>>>(Hpre, dec1_v0, dec1_v1);
    gat_agg3<<<NN, 128>>>(Hpre);   // -> g_Ahi/g_Alo [4096,512]

    // 5. recon = Hagg @ dec2_W + b (grid already 256; unchanged this round)
    pack_tB<<<(HH1 * GG + 255) / 256, 256>>>(dec2_W, HH1, GG);
    gemm_hmma<128, 128><<<dim3(8, 32, 1), 256, SM128>>>(
        Ahi, Alo, dec2_b, out_recon, HH1, HH1, GG);
}

// round 10
// speedup vs baseline: 2.0619x; 1.3452x over previous
#include <cuda_runtime.h>
#include <cuda_fp16.h>
#include <math.h>
#include <stdint.h>

#define NN 4096
#define GG 1024
#define HH1 512
#define HH2 64
#define NHEAD 4
#define CHAN 128
#define SEDIM 16
#define CAP 256
#define KP_DEC 128

// ---------------- scratch (static device globals; no allocation) ----------
__device__ __half g_A16[NN * GG];          // activations, single fp16
__device__ __half g_W1h[HH1 * GG],     g_W1l[HH1 * GG];      // enc1 [512][1024]
__device__ __half g_W2h[HH2 * HH1],    g_W2l[HH2 * HH1];     // enc2 [64][512]
__device__ __half g_W3h[HH1 * KP_DEC], g_W3l[HH1 * KP_DEC];  // dec1 [512][128]
__device__ __half g_W4h[GG * HH1],     g_W4l[GG * HH1];      // dec2 [1024][512]
__device__ float g_Hpre[NN * HH1];
__device__ float g_P0[NN * GG];            // split-K partials (2 x NN x HH1)
__device__ float g_f1[NHEAD * NN];
__device__ float g_f2[NHEAD * NN];
__device__ int   g_cols[NN * CAP];
__device__ int   g_cnt[NN];

// ---------------- helpers ---------------------------------------------------
__device__ __forceinline__ void hsplit(float x, __half* h, __half* l) {
    __half hh = __float2half_rn(x);
    *h = hh;
    *l = __float2half_rn(x - __half2float(hh));
}
__device__ __forceinline__ uint32_t smem_u32(const void* p) {
    uint32_t a;
    asm("{ .reg .u64 t; cvta.to.shared.u64 t, %1; cvt.u32.u64 %0, t; }" : "=r"(a) : "l"(p));
    return a;
}
#define LDM4(r, addr) \
    asm volatile("ldmatrix.sync.aligned.m8n8.x4.shared.b16 {%0,%1,%2,%3}, [%4];" \
                 : "=r"((r)[0]), "=r"((r)[1]), "=r"((r)[2]), "=r"((r)[3]) : "r"(addr))
#define MMAF16(d, a, b0_, b1_) \
    asm volatile("mma.sync.aligned.m16n8k16.row.col.f32.f16.f16.f32 " \
                 "{%0,%1,%2,%3}, {%4,%5,%6,%7}, {%8,%9}, {%0,%1,%2,%3};" \
                 : "+f"((d)[0]), "+f"((d)[1]), "+f"((d)[2]), "+f"((d)[3]) \
                 : "r"((a)[0]), "r"((a)[1]), "r"((a)[2]), "r"((a)[3]), "r"(b0_), "r"(b1_))
#define CP16(dst, src) \
    asm volatile("cp.async.cg.shared.global [%0], [%1], 16;" :: "r"(dst), "l"(src))

// ---------------- fused prologue: csr + A16 convert + all weight packs -----
__global__ void __launch_bounds__(256) prologue(
    const float* __restrict__ adj, const float4* __restrict__ node,
    const float* __restrict__ enc1_W, const float* __restrict__ enc2_W,
    const float* __restrict__ dec1_W, const float* __restrict__ dec2_W) {
    __shared__ int cnt;
    int b = blockIdx.x, tid = threadIdx.x;
    if (b < 4096) {
        // CSR row b
        if (tid == 0) cnt = 0;
        __syncthreads();
        const float4* arow = (const float4*)(adj + (size_t)b * NN);
        for (int j4 = tid; j4 < NN / 4; j4 += 256) {
            float4 v = arow[j4];
            if (v.x != 0.f) { int k = atomicAdd(&cnt, 1); if (k < CAP) g_cols[b * CAP + k] = j4 * 4 + 0; }
            if (v.y != 0.f) { int k = atomicAdd(&cnt, 1); if (k < CAP) g_cols[b * CAP + k] = j4 * 4 + 1; }
            if (v.z != 0.f) { int k = atomicAdd(&cnt, 1); if (k < CAP) g_cols[b * CAP + k] = j4 * 4 + 2; }
            if (v.w != 0.f) { int k = atomicAdd(&cnt, 1); if (k < CAP) g_cols[b * CAP + k] = j4 * 4 + 3; }
        }
        __syncthreads();
        if (tid == 0) g_cnt[b] = min(cnt, CAP);
    } else if (b < 8192) {
        // node feats -> fp16
        int i = (b - 4096) * 256 + tid;          // over NN*GG/4
        float4 v = node[i];
        __half2 h0 = __floats2half2_rn(v.x, v.y);
        __half2 h1 = __floats2half2_rn(v.z, v.w);
        uint2 u;
        u.x = *reinterpret_cast<uint32_t*>(&h0);
        u.y = *reinterpret_cast<uint32_t*>(&h1);
        *(uint2*)(g_A16 + (size_t)i * 4) = u;
    } else if (b < 10240) {
        // enc1 pack: [NH,1024,128] -> [512][1024]
        int idx = (b - 8192) * 256 + tid;
        int n = idx >> 10, k = idx & 1023;
        float v = enc1_W[((size_t)(n >> 7) * GG + k) * CHAN + (n & 127)];
        hsplit(v, &g_W1h[idx], &g_W1l[idx]);
    } else if (b < 10368) {
        // enc2 transpose: [512,64] -> [64][512]
        int idx = (b - 10240) * 256 + tid;
        int n = idx >> 9, k = idx & 511;
        hsplit(enc2_W[k * HH2 + n], &g_W2h[idx], &g_W2l[idx]);
    } else if (b < 10624) {
        // dec1 pack: [NH,80,128] -> [512][128] zero-padded
        int idx = (b - 10368) * 256 + tid;
        int n = idx >> 7, k = idx & 127;
        float v = (k < HH2 + SEDIM)
                      ? dec1_W[((size_t)(n >> 7) * (HH2 + SEDIM) + k) * CHAN + (n & 127)]
                      : 0.f;
        hsplit(v, &g_W3h[idx], &g_W3l[idx]);
    } else {
        // dec2 transpose: [512,1024] -> [1024][512]
        int idx = (b - 10624) * 256 + tid;
        int n = idx >> 9, k = idx & 511;
        hsplit(dec2_W[(size_t)k * GG + n], &g_W4h[idx], &g_W4l[idx]);
    }
}

// ---------------- split-K partial reduce + bias ----------------------------
__global__ void reduceP(const float4* __restrict__ P, float4* __restrict__ out,
                        const float4* __restrict__ bias, int NcDiv4, int nsplit,
                        int total4) {
    int idx = blockIdx.x * blockDim.x + threadIdx.x;
    if (idx >= total4) return;
    float4 s = P[idx];
    for (int k = 1; k < nsplit; k++) {
        float4 q = P[idx + k * total4];
        s.x += q.x; s.y += q.y; s.z += q.z; s.w += q.w;
    }
    float4 b = bias[idx & (NcDiv4 - 1)];
    s.x += b.x; s.y += b.y; s.z += b.z; s.w += b.w;
    out[idx] = s;
}

// ---------------- HMMA fp16 2-term GEMM, MTILE x NT tiles -------------------
// C[4096,Nc] = A16[4096,K] @ (Bh+Bl)[Nc,K]^T (+ bias or raw split-K partial)
template <int MTILE, int NT>
__global__ void __launch_bounds__(256, 2)
gemm2(const __half* __restrict__ A, const __half* __restrict__ Bh_,
      const __half* __restrict__ Bl_, const float* __restrict__ bias,
      float* __restrict__ C, int Kfull, int Ksplit, int Nc) {
    constexpr int WMW = 2;                       // warps along m (MTILE==128)
    constexpr int WNW = 4;
    constexpr int WM  = MTILE / WMW;             // 64
    constexpr int WN  = NT / WNW;                // 32 or 16
    constexpr int MT  = WM / 16;                 // 4
    constexpr int NTL = WN / 8;                  // 4 or 2
    constexpr int NP  = NTL / 2;                 // 2 or 1
    constexpr int ASZ = MTILE * 80;
    constexpr int BSZ = NT * 80;
    constexpr int STG = ASZ + 2 * BSZ;
    constexpr int AJ  = MTILE / 64;              // 2
    constexpr int BJ  = NT / 64;                 // 2 or 1

    extern __shared__ char sm[];
    const int tid = threadIdx.x, lane = tid & 31, wid = tid >> 5;
    const int m0 = blockIdx.y * MTILE, n0 = blockIdx.x * NT;
    const int koff = blockIdx.z * Ksplit;
    const int wm0 = (wid % WMW) * WM, wn0 = (wid / WMW) * WN;

    const int ar = tid >> 1, ac = (tid & 1) * 16;                 // AJ==2
    const size_t abase = (size_t)(m0 + ar) * Kfull + koff + ac;
    const int br = (BJ == 2) ? (tid >> 1) : (tid >> 2);
    const int bc = (BJ == 2) ? ((tid & 1) * 16) : ((tid & 3) * 8);
    const size_t bbase = (size_t)(n0 + br) * Kfull + koff + bc;

    const uint32_t sA = smem_u32(sm);
    const uint32_t stA = ar * 80 + ac * 2;
    const uint32_t stB = br * 80 + bc * 2;

    const int lr = lane & 15, lk = (lane >> 4) * 8;
    const uint32_t aoff = (wm0 + lr) * 80 + lk * 2;
    const uint32_t boff = (wn0 + lr) * 80 + lk * 2;

    float acc[MT][NTL][4];
#pragma unroll
    for (int i = 0; i < MT; i++)
#pragma unroll
        for (int j = 0; j < NTL; j++)
#pragma unroll
            for (int q = 0; q < 4; q++) acc[i][j][q] = 0.f;

    const int NC = Ksplit >> 5;

#define GLOADC(c0, buf)                                                        \
    {                                                                          \
        int k0 = (c0) * 32;                                                    \
        uint32_t d = sA + (buf) * STG;                                         \
        _Pragma("unroll") for (int j = 0; j < AJ; j++)                         \
            CP16(d + stA + j * 16, A + abase + k0 + j * 8);                    \
        _Pragma("unroll") for (int j = 0; j < BJ; j++) {                       \
            CP16(d + ASZ + stB + j * 16, Bh_ + bbase + k0 + j * 8);            \
            CP16(d + ASZ + BSZ + stB + j * 16, Bl_ + bbase + k0 + j * 8);      \
        }                                                                      \
        asm volatile("cp.async.commit_group;" ::: "memory");                   \
    }

    GLOADC(0, 0);
    for (int c = 0; c < NC; c++) {
        if (c + 1 < NC) {
            GLOADC(c + 1, (c + 1) & 1);
            asm volatile("cp.async.wait_group 1;" ::: "memory");
        } else {
            asm volatile("cp.async.wait_group 0;" ::: "memory");
        }
        __syncthreads();
        uint32_t uA  = sA + (c & 1) * STG;
        uint32_t uBh = uA + ASZ;
        uint32_t uBl = uBh + BSZ;
#pragma unroll
        for (int ks = 0; ks < 2; ks++) {
            uint32_t a_[MT][4], bh[NP][4], bl[NP][4];
#pragma unroll
            for (int mt = 0; mt < MT; mt++) LDM4(a_[mt], uA + aoff + mt * 1280 + ks * 32);
#pragma unroll
            for (int p = 0; p < NP; p++) LDM4(bh[p], uBh + boff + p * 1280 + ks * 32);
#pragma unroll
            for (int p = 0; p < NP; p++) LDM4(bl[p], uBl + boff + p * 1280 + ks * 32);
            // term 1: a * b_hi
#pragma unroll
            for (int mt = 0; mt < MT; mt++)
#pragma unroll
                for (int p = 0; p < NP; p++) {
                    MMAF16(acc[mt][2 * p],     a_[mt], bh[p][0], bh[p][2]);
                    MMAF16(acc[mt][2 * p + 1], a_[mt], bh[p][1], bh[p][3]);
                }
            // term 2: a * b_lo
#pragma unroll
            for (int mt = 0; mt < MT; mt++)
#pragma unroll
                for (int p = 0; p < NP; p++) {
                    MMAF16(acc[mt][2 * p],     a_[mt], bl[p][0], bl[p][2]);
                    MMAF16(acc[mt][2 * p + 1], a_[mt], bl[p][1], bl[p][3]);
                }
        }
        __syncthreads();
    }
#undef GLOADC

    // epilogue
    float* Cz = C + (size_t)blockIdx.z * NN * Nc;
    int g = lane >> 2, tg = lane & 3;
#pragma unroll
    for (int mt = 0; mt < MT; mt++) {
        int row = m0 + wm0 + mt * 16 + g;
#pragma unroll
        for (int nt = 0; nt < NTL; nt++) {
            int col = n0 + wn0 + nt * 8 + tg * 2;
            float b0 = bias ? bias[col] : 0.f, b1 = bias ? bias[col + 1] : 0.f;
            Cz[(size_t)row * Nc + col]           = acc[mt][nt][0] + b0;
            Cz[(size_t)row * Nc + col + 1]       = acc[mt][nt][1] + b1;
            Cz[(size_t)(row + 8) * Nc + col]     = acc[mt][nt][2] + b0;
            Cz[(size_t)(row + 8) * Nc + col + 1] = acc[mt][nt][3] + b1;
        }
    }
}

// ---------------- attention features f1 = h@v0, f2 = h@v1 ------------------
__global__ void __launch_bounds__(512) feats2(const float* __restrict__ Hpre,
                                              const float* __restrict__ v0,
                                              const float* __restrict__ v1) {
    int tid = threadIdx.x, wid = tid >> 5, lid = tid & 31;
    int n = blockIdx.x * 4 + (wid >> 2);
    int h = wid & 3;
    float4 hv = *(const float4*)(Hpre + (size_t)n * HH1 + h * CHAN + lid * 4);
    float4 a  = *(const float4*)(v0 + h * CHAN + lid * 4);
    float4 b  = *(const float4*)(v1 + h * CHAN + lid * 4);
    float s1 = hv.x * a.x + hv.y * a.y + hv.z * a.z + hv.w * a.w;
    float s2 = hv.x * b.x + hv.y * b.y + hv.z * b.z + hv.w * b.w;
#pragma unroll
    for (int o = 16; o > 0; o >>= 1) {
        s1 += __shfl_down_sync(0xffffffffu, s1, o);
        s2 += __shfl_down_sync(0xffffffffu, s2, o);
    }
    if (lid == 0) {
        g_f1[h * NN + n] = s1;
        g_f2[h * NN + n] = s2;
    }
}

// ---------------- sparse attention softmax + aggregation + ELU -------------
// warp = one (row, head); register softmax; writes fp16 activations
__global__ void __launch_bounds__(128) gat_agg3(const float* __restrict__ Hpre) {
    int row = blockIdx.x, tid = threadIdx.x, wid = tid >> 5, lid = tid & 31;
    int cnt = g_cnt[row];
    const int* cols = g_cols + row * CAP;
    const float* f2h = g_f2 + wid * NN;
    float f1r = g_f1[wid * NN + row];
    const float* Hb = Hpre + wid * CHAN + lid * 4;
    float4 acc = {0.f, 0.f, 0.f, 0.f};
    float inv;

    if (cnt <= 32) {
        bool valid = lid < cnt;
        int col = valid ? cols[lid] : 0;
        float u = 0.f;
        if (valid) {
            float x = f1r + f2h[col];
            u = 1.f / (1.f + expf(-x)) - 0.5f;
        }
        float mv = (valid && u != 0.f) ? u : -1e30f;
#pragma unroll
        for (int o = 16; o; o >>= 1) mv = fmaxf(mv, __shfl_xor_sync(0xffffffffu, mv, o));
        float e = (valid && u != 0.f) ? expf(u - mv) : 0.f;
        float s = e;
#pragma unroll
        for (int o = 16; o; o >>= 1) s += __shfl_xor_sync(0xffffffffu, s, o);
        inv = 1.f / fmaxf(s, 1e-30f);
        for (int k = 0; k < cnt; k++) {
            float w = __shfl_sync(0xffffffffu, e, k);
            int c2 = __shfl_sync(0xffffffffu, col, k);
            if (w != 0.f) {
                float4 hv = *(const float4*)(Hb + (size_t)c2 * HH1);
                acc.x += w * hv.x; acc.y += w * hv.y;
                acc.z += w * hv.z; acc.w += w * hv.w;
            }
        }
    } else {
        float mv = -1e30f;
        for (int c0 = 0; c0 < cnt; c0 += 32) {
            int k = c0 + lid;
            if (k < cnt) {
                float x = f1r + f2h[cols[k]];
                float u = 1.f / (1.f + expf(-x)) - 0.5f;
                if (u != 0.f) mv = fmaxf(mv, u);
            }
        }
#pragma unroll
        for (int o = 16; o; o >>= 1) mv = fmaxf(mv, __shfl_xor_sync(0xffffffffu, mv, o));
        float s = 0.f;
        for (int c0 = 0; c0 < cnt; c0 += 32) {
            int k = c0 + lid;
            if (k < cnt) {
                float x = f1r + f2h[cols[k]];
                float u = 1.f / (1.f + expf(-x)) - 0.5f;
                if (u != 0.f) s += expf(u - mv);
            }
        }
#pragma unroll
        for (int o = 16; o; o >>= 1) s += __shfl_xor_sync(0xffffffffu, s, o);
        inv = 1.f / fmaxf(s, 1e-30f);
        for (int c0 = 0; c0 < cnt; c0 += 32) {
            int k = c0 + lid;
            int col = (k < cnt) ? cols[k] : 0;
            float e = 0.f;
            if (k < cnt) {
                float x = f1r + f2h[col];
                float u = 1.f / (1.f + expf(-x)) - 0.5f;
                if (u != 0.f) e = expf(u - mv);
            }
            int lim = min(32, cnt - c0);
            for (int j = 0; j < lim; j++) {
                float w = __shfl_sync(0xffffffffu, e, j);
                int c2 = __shfl_sync(0xffffffffu, col, j);
                if (w != 0.f) {
                    float4 hv = *(const float4*)(Hb + (size_t)c2 * HH1);
                    acc.x += w * hv.x; acc.y += w * hv.y;
                    acc.z += w * hv.z; acc.w += w * hv.w;
                }
            }
        }
    }

    acc.x *= inv; acc.y *= inv; acc.z *= inv; acc.w *= inv;
    acc.x = (acc.x > 0.f) ? acc.x : expm1f(acc.x);
    acc.y = (acc.y > 0.f) ? acc.y : expm1f(acc.y);
    acc.z = (acc.z > 0.f) ? acc.z : expm1f(acc.z);
    acc.w = (acc.w > 0.f) ? acc.w : expm1f(acc.w);
    __half2 p0 = __floats2half2_rn(acc.x, acc.y);
    __half2 p1 = __floats2half2_rn(acc.z, acc.w);
    uint2 u;
    u.x = *reinterpret_cast<uint32_t*>(&p0);
    u.y = *reinterpret_cast<uint32_t*>(&p1);
    *(uint2*)(g_A16 + (size_t)row * HH1 + wid * CHAN + lid * 4) = u;
}

// ---------------- Hd = concat(Z, emb[slice], zero-pad to 128) -> fp16 ------
__global__ void build_hd(const float* __restrict__ Z,
                         const int* __restrict__ slice,
                         const float* __restrict__ emb) {
    int n = blockIdx.x, t = threadIdx.x;  // 128 threads
    float v = 0.f;
    if (t < HH2) v = Z[(size_t)n * HH2 + t];
    else if (t < HH2 + SEDIM) v = emb[slice[n] * SEDIM + (t - HH2)];
    g_A16[(size_t)n * KP_DEC + t] = __float2half_rn(v);
}

extern "C" void kernel_launch(void* const* d_in, const int* in_sizes, int n_in,
                              void* d_out, int out_size) {
    const float* adj     = (const float*)d_in[0];
    const float* node    = (const float*)d_in[1];
    const int*   slice   = (const int*)d_in[4];
    const float* enc1_W  = (const float*)d_in[6];
    const float* enc1_b  = (const float*)d_in[7];
    const float* enc1_v0 = (const float*)d_in[8];
    const float* enc1_v1 = (const float*)d_in[9];
    const float* enc2_W  = (const float*)d_in[10];
    const float* enc2_b  = (const float*)d_in[11];
    const float* dec1_W  = (const float*)d_in[12];
    const float* dec1_b  = (const float*)d_in[13];
    const float* dec1_v0 = (const float*)d_in[14];
    const float* dec1_v1 = (const float*)d_in[15];
    const float* dec2_W  = (const float*)d_in[16];
    const float* dec2_b  = (const float*)d_in[17];
    const float* emb     = (const float*)d_in[18];

    float* out_recon = (float*)d_out;                   // [N, G]
    float* out_Z     = (float*)d_out + (size_t)NN * GG; // [N, H2]

    float* Hpre; cudaGetSymbolAddress((void**)&Hpre, g_Hpre);
    float* P0;   cudaGetSymbolAddress((void**)&P0, g_P0);
    __half* A16; cudaGetSymbolAddress((void**)&A16, g_A16);
    __half* W1h; cudaGetSymbolAddress((void**)&W1h, g_W1h);
    __half* W1l; cudaGetSymbolAddress((void**)&W1l, g_W1l);
    __half* W2h; cudaGetSymbolAddress((void**)&W2h, g_W2h);
    __half* W2l; cudaGetSymbolAddress((void**)&W2l, g_W2l);
    __half* W3h; cudaGetSymbolAddress((void**)&W3h, g_W3h);
    __half* W3l; cudaGetSymbolAddress((void**)&W3l, g_W3l);
    __half* W4h; cudaGetSymbolAddress((void**)&W4h, g_W4h);
    __half* W4l; cudaGetSymbolAddress((void**)&W4l, g_W4l);

    const int SM128 = 2 * (128 * 80 + 2 * 128 * 80); // 61440
    const int SM64  = 2 * (128 * 80 + 2 * 64 * 80);  // 40960
    cudaFuncSetAttribute((const void*)gemm2<128, 128>,
                         cudaFuncAttributeMaxDynamicSharedMemorySize, SM128);
    cudaFuncSetAttribute((const void*)gemm2<128, 64>,
                         cudaFuncAttributeMaxDynamicSharedMemorySize, SM64);

    // 0. fused prologue: CSR + fp16 convert + all weight packs
    prologue<<<12672, 256>>>(adj, (const float4*)node,
                             enc1_W, enc2_W, dec1_W, dec2_W);

    // 1. enc1 GEMM (K=1024, split-K=2) + reduce
    gemm2<128, 128><<<dim3(4, 32, 2), 256, SM128>>>(
        A16, W1h, W1l, nullptr, P0, GG, GG / 2, HH1);
    reduceP<<<(NN * HH1 / 4 + 255) / 256, 256>>>(
        (const float4*)P0, (float4*)Hpre, (const float4*)enc1_b, HH1 / 4, 2, NN * HH1 / 4);
    feats2<<<NN / 4, 512>>>(Hpre, enc1_v0, enc1_v1);
    gat_agg3<<<NN, 128>>>(Hpre);   // -> g_A16 [4096,512] fp16

    // 2. Z GEMM (K=512, split-K=4) + reduce into output tail
    gemm2<128, 64><<<dim3(1, 32, 4), 256, SM64>>>(
        A16, W2h, W2l, nullptr, P0, HH1, HH1 / 4, HH2);
    reduceP<<<(NN * HH2 / 4 + 255) / 256, 256>>>(
        (const float4*)P0, (float4*)out_Z, (const float4*)enc2_b, HH2 / 4, 4, NN * HH2 / 4);

    // 3. decoder GAT layer (K=128)
    build_hd<<<NN, 128>>>(out_Z, slice, emb);   // -> g_A16 [4096,128]
    gemm2<128, 128><<<dim3(4, 32, 1), 256, SM128>>>(
        A16, W3h, W3l, dec1_b, Hpre, KP_DEC, KP_DEC, HH1);
    feats2<<<NN / 4, 512>>>(Hpre, dec1_v0, dec1_v1);
    gat_agg3<<<NN, 128>>>(Hpre);   // -> g_A16 [4096,512]

    // 4. recon GEMM (K=512)
    gemm2<128, 128><<<dim3(8, 32, 1), 256, SM128>>>(
        A16, W4h, W4l, dec2_b, out_recon, HH1, HH1, GG);
}

// round 11
// speedup vs baseline: 2.1030x; 1.0199x over previous
#include <cuda_runtime.h>
#include <cuda_fp16.h>
#include <math.h>
#include <stdint.h>

#define NN 4096
#define GG 1024
#define HH1 512
#define HH2 64
#define NHEAD 4
#define CHAN 128
#define SEDIM 16
#define CAP 256
#define KP_DEC 128

// ---------------- scratch (static device globals; no allocation) ----------
__device__ __half g_A16[NN * GG];          // activations, single fp16
__device__ __half g_H16[NN * HH1];         // GAT pre-activation H, fp16 (for agg)
__device__ __half g_W1h[HH1 * GG],     g_W1l[HH1 * GG];      // enc1 [512][1024]
__device__ __half g_W2h[HH2 * HH1],    g_W2l[HH2 * HH1];     // enc2 [64][512]
__device__ __half g_W3h[HH1 * KP_DEC], g_W3l[HH1 * KP_DEC];  // dec1 [512][128]
__device__ __half g_W4h[GG * HH1],     g_W4l[GG * HH1];      // dec2 [1024][512]
__device__ float g_Hpre[NN * HH1];
__device__ float g_P0[NN * GG];            // split-K partials (2 x NN x HH1)
__device__ float g_f1[NHEAD * NN];
__device__ float g_f2[NHEAD * NN];
__device__ int   g_cols[NN * CAP];
__device__ int   g_cnt[NN];

// ---------------- helpers ---------------------------------------------------
__device__ __forceinline__ void hsplit(float x, __half* h, __half* l) {
    __half hh = __float2half_rn(x);
    *h = hh;
    *l = __float2half_rn(x - __half2float(hh));
}
__device__ __forceinline__ uint32_t smem_u32(const void* p) {
    uint32_t a;
    asm("{ .reg .u64 t; cvta.to.shared.u64 t, %1; cvt.u32.u64 %0, t; }" : "=r"(a) : "l"(p));
    return a;
}
#define LDM4(r, addr) \
    asm volatile("ldmatrix.sync.aligned.m8n8.x4.shared.b16 {%0,%1,%2,%3}, [%4];" \
                 : "=r"((r)[0]), "=r"((r)[1]), "=r"((r)[2]), "=r"((r)[3]) : "r"(addr))
#define MMAF16(d, a, b0_, b1_) \
    asm volatile("mma.sync.aligned.m16n8k16.row.col.f32.f16.f16.f32 " \
                 "{%0,%1,%2,%3}, {%4,%5,%6,%7}, {%8,%9}, {%0,%1,%2,%3};" \
                 : "+f"((d)[0]), "+f"((d)[1]), "+f"((d)[2]), "+f"((d)[3]) \
                 : "r"((a)[0]), "r"((a)[1]), "r"((a)[2]), "r"((a)[3]), "r"(b0_), "r"(b1_))
#define CP16(dst, src) \
    asm volatile("cp.async.cg.shared.global [%0], [%1], 16;" :: "r"(dst), "l"(src))

// ---------------- fused prologue: csr + A16 convert + all weight packs -----
__global__ void __launch_bounds__(256) prologue(
    const float* __restrict__ adj, const float4* __restrict__ node,
    const float* __restrict__ enc1_W, const float* __restrict__ enc2_W,
    const float* __restrict__ dec1_W, const float* __restrict__ dec2_W) {
    __shared__ int cnt;
    int b = blockIdx.x, tid = threadIdx.x;
    if (b < 4096) {
        // CSR row b
        if (tid == 0) cnt = 0;
        __syncthreads();
        const float4* arow = (const float4*)(adj + (size_t)b * NN);
        for (int j4 = tid; j4 < NN / 4; j4 += 256) {
            float4 v = arow[j4];
            if (v.x != 0.f) { int k = atomicAdd(&cnt, 1); if (k < CAP) g_cols[b * CAP + k] = j4 * 4 + 0; }
            if (v.y != 0.f) { int k = atomicAdd(&cnt, 1); if (k < CAP) g_cols[b * CAP + k] = j4 * 4 + 1; }
            if (v.z != 0.f) { int k = atomicAdd(&cnt, 1); if (k < CAP) g_cols[b * CAP + k] = j4 * 4 + 2; }
            if (v.w != 0.f) { int k = atomicAdd(&cnt, 1); if (k < CAP) g_cols[b * CAP + k] = j4 * 4 + 3; }
        }
        __syncthreads();
        if (tid == 0) g_cnt[b] = min(cnt, CAP);
    } else if (b < 8192) {
        // node feats -> fp16
        int i = (b - 4096) * 256 + tid;          // over NN*GG/4
        float4 v = node[i];
        __half2 h0 = __floats2half2_rn(v.x, v.y);
        __half2 h1 = __floats2half2_rn(v.z, v.w);
        uint2 u;
        u.x = *reinterpret_cast<uint32_t*>(&h0);
        u.y = *reinterpret_cast<uint32_t*>(&h1);
        *(uint2*)(g_A16 + (size_t)i * 4) = u;
    } else if (b < 10240) {
        // enc1 pack: [NH,1024,128] -> [512][1024]
        int idx = (b - 8192) * 256 + tid;
        int n = idx >> 10, k = idx & 1023;
        float v = enc1_W[((size_t)(n >> 7) * GG + k) * CHAN + (n & 127)];
        hsplit(v, &g_W1h[idx], &g_W1l[idx]);
    } else if (b < 10368) {
        // enc2 transpose: [512,64] -> [64][512]
        int idx = (b - 10240) * 256 + tid;
        int n = idx >> 9, k = idx & 511;
        hsplit(enc2_W[k * HH2 + n], &g_W2h[idx], &g_W2l[idx]);
    } else if (b < 10624) {
        // dec1 pack: [NH,80,128] -> [512][128] zero-padded
        int idx = (b - 10368) * 256 + tid;
        int n = idx >> 7, k = idx & 127;
        float v = (k < HH2 + SEDIM)
                      ? dec1_W[((size_t)(n >> 7) * (HH2 + SEDIM) + k) * CHAN + (n & 127)]
                      : 0.f;
        hsplit(v, &g_W3h[idx], &g_W3l[idx]);
    } else {
        // dec2 transpose: [512,1024] -> [1024][512]
        int idx = (b - 10624) * 256 + tid;
        int n = idx >> 9, k = idx & 511;
        hsplit(dec2_W[(size_t)k * GG + n], &g_W4h[idx], &g_W4l[idx]);
    }
}

// ---------------- split-K partial reduce + bias (generic, for Z) -----------
__global__ void reduceP(const float4* __restrict__ P, float4* __restrict__ out,
                        const float4* __restrict__ bias, int NcDiv4, int nsplit,
                        int total4) {
    int idx = blockIdx.x * blockDim.x + threadIdx.x;
    if (idx >= total4) return;
    float4 s = P[idx];
    for (int k = 1; k < nsplit; k++) {
        float4 q = P[idx + k * total4];
        s.x += q.x; s.y += q.y; s.z += q.z; s.w += q.w;
    }
    float4 b = bias[idx & (NcDiv4 - 1)];
    s.x += b.x; s.y += b.y; s.z += b.z; s.w += b.w;
    out[idx] = s;
}

// ---------------- enc1 fused reduce: partials + bias -> H16 + f1/f2 --------
// One warp covers exactly one (row, head) x 128 channels; shfl reduces f1/f2.
__global__ void __launch_bounds__(256) reduceF(
    const float4* __restrict__ P, const float4* __restrict__ bias,
    const float4* __restrict__ v0, const float4* __restrict__ v1) {
    const int idx = blockIdx.x * 256 + threadIdx.x;      // over NN*HH1/4
    const int row = idx >> 7, col4 = idx & 127;
    const int lid = threadIdx.x & 31;
    constexpr int T4 = NN * HH1 / 4;
    float4 s = P[idx];
    float4 q = P[idx + T4];
    s.x += q.x; s.y += q.y; s.z += q.z; s.w += q.w;
    float4 b = bias[col4];
    s.x += b.x; s.y += b.y; s.z += b.z; s.w += b.w;
    // fp16 copy for aggregation
    __half2 h0 = __floats2half2_rn(s.x, s.y);
    __half2 h1 = __floats2half2_rn(s.z, s.w);
    uint2 u;
    u.x = *reinterpret_cast<uint32_t*>(&h0);
    u.y = *reinterpret_cast<uint32_t*>(&h1);
    *(uint2*)(g_H16 + (size_t)idx * 4) = u;
    // attention features
    float4 a = v0[col4], c = v1[col4];
    float s1 = s.x * a.x + s.y * a.y + s.z * a.z + s.w * a.w;
    float s2 = s.x * c.x + s.y * c.y + s.z * c.z + s.w * c.w;
#pragma unroll
    for (int o = 16; o > 0; o >>= 1) {
        s1 += __shfl_down_sync(0xffffffffu, s1, o);
        s2 += __shfl_down_sync(0xffffffffu, s2, o);
    }
    if (lid == 0) {
        int h = col4 >> 5;
        g_f1[h * NN + row] = s1;
        g_f2[h * NN + row] = s2;
    }
}

// ---------------- HMMA fp16 2-term GEMM, MTILE x NT tiles -------------------
// C = A16 @ (Bh+Bl)^T (+ bias or raw split-K partial). WH: also write H16.
template <int MTILE, int NT, bool WH>
__global__ void __launch_bounds__(256, 2)
gemm2(const __half* __restrict__ A, const __half* __restrict__ Bh_,
      const __half* __restrict__ Bl_, const float* __restrict__ bias,
      float* __restrict__ C, int Kfull, int Ksplit, int Nc) {
    constexpr int WMW = 2;
    constexpr int WNW = 4;
    constexpr int WM  = MTILE / WMW;             // 64
    constexpr int WN  = NT / WNW;
    constexpr int MT  = WM / 16;                 // 4
    constexpr int NTL = WN / 8;
    constexpr int NP  = NTL / 2;
    constexpr int ASZ = MTILE * 80;
    constexpr int BSZ = NT * 80;
    constexpr int STG = ASZ + 2 * BSZ;
    constexpr int AJ  = MTILE / 64;              // 2
    constexpr int BJ  = NT / 64;

    extern __shared__ char sm[];
    const int tid = threadIdx.x, lane = tid & 31, wid = tid >> 5;
    const int m0 = blockIdx.y * MTILE, n0 = blockIdx.x * NT;
    const int koff = blockIdx.z * Ksplit;
    const int wm0 = (wid % WMW) * WM, wn0 = (wid / WMW) * WN;

    const int ar = tid >> 1, ac = (tid & 1) * 16;
    const size_t abase = (size_t)(m0 + ar) * Kfull + koff + ac;
    const int br = (BJ == 2) ? (tid >> 1) : (tid >> 2);
    const int bc = (BJ == 2) ? ((tid & 1) * 16) : ((tid & 3) * 8);
    const size_t bbase = (size_t)(n0 + br) * Kfull + koff + bc;

    const uint32_t sA = smem_u32(sm);
    const uint32_t stA = ar * 80 + ac * 2;
    const uint32_t stB = br * 80 + bc * 2;

    const int lr = lane & 15, lk = (lane >> 4) * 8;
    const uint32_t aoff = (wm0 + lr) * 80 + lk * 2;
    const uint32_t boff = (wn0 + lr) * 80 + lk * 2;

    float acc[MT][NTL][4];
#pragma unroll
    for (int i = 0; i < MT; i++)
#pragma unroll
        for (int j = 0; j < NTL; j++)
#pragma unroll
            for (int q = 0; q < 4; q++) acc[i][j][q] = 0.f;

    const int NC = Ksplit >> 5;

#define GLOADC(c0, buf)                                                        \
    {                                                                          \
        int k0 = (c0) * 32;                                                    \
        uint32_t d = sA + (buf) * STG;                                         \
        _Pragma("unroll") for (int j = 0; j < AJ; j++)                         \
            CP16(d + stA + j * 16, A + abase + k0 + j * 8);                    \
        _Pragma("unroll") for (int j = 0; j < BJ; j++) {                       \
            CP16(d + ASZ + stB + j * 16, Bh_ + bbase + k0 + j * 8);            \
            CP16(d + ASZ + BSZ + stB + j * 16, Bl_ + bbase + k0 + j * 8);      \
        }                                                                      \
        asm volatile("cp.async.commit_group;" ::: "memory");                   \
    }

    GLOADC(0, 0);
    for (int c = 0; c < NC; c++) {
        if (c + 1 < NC) {
            GLOADC(c + 1, (c + 1) & 1);
            asm volatile("cp.async.wait_group 1;" ::: "memory");
        } else {
            asm volatile("cp.async.wait_group 0;" ::: "memory");
        }
        __syncthreads();
        uint32_t uA  = sA + (c & 1) * STG;
        uint32_t uBh = uA + ASZ;
        uint32_t uBl = uBh + BSZ;
#pragma unroll
        for (int ks = 0; ks < 2; ks++) {
            uint32_t a_[MT][4], bh[NP][4], bl[NP][4];
#pragma unroll
            for (int mt = 0; mt < MT; mt++) LDM4(a_[mt], uA + aoff + mt * 1280 + ks * 32);
#pragma unroll
            for (int p = 0; p < NP; p++) LDM4(bh[p], uBh + boff + p * 1280 + ks * 32);
#pragma unroll
            for (int p = 0; p < NP; p++) LDM4(bl[p], uBl + boff + p * 1280 + ks * 32);
            // term 1: a * b_hi
#pragma unroll
            for (int mt = 0; mt < MT; mt++)
#pragma unroll
                for (int p = 0; p < NP; p++) {
                    MMAF16(acc[mt][2 * p],     a_[mt], bh[p][0], bh[p][2]);
                    MMAF16(acc[mt][2 * p + 1], a_[mt], bh[p][1], bh[p][3]);
                }
            // term 2: a * b_lo
#pragma unroll
            for (int mt = 0; mt < MT; mt++)
#pragma unroll
                for (int p = 0; p < NP; p++) {
                    MMAF16(acc[mt][2 * p],     a_[mt], bl[p][0], bl[p][2]);
                    MMAF16(acc[mt][2 * p + 1], a_[mt], bl[p][1], bl[p][3]);
                }
        }
        __syncthreads();
    }
#undef GLOADC

    // epilogue
    float* Cz = C + (size_t)blockIdx.z * NN * Nc;
    int g = lane >> 2, tg = lane & 3;
#pragma unroll
    for (int mt = 0; mt < MT; mt++) {
        int row = m0 + wm0 + mt * 16 + g;
#pragma unroll
        for (int nt = 0; nt < NTL; nt++) {
            int col = n0 + wn0 + nt * 8 + tg * 2;
            float b0 = bias ? bias[col] : 0.f, b1 = bias ? bias[col + 1] : 0.f;
            float c0 = acc[mt][nt][0] + b0, c1 = acc[mt][nt][1] + b1;
            float c2 = acc[mt][nt][2] + b0, c3 = acc[mt][nt][3] + b1;
            Cz[(size_t)row * Nc + col]           = c0;
            Cz[(size_t)row * Nc + col + 1]       = c1;
            Cz[(size_t)(row + 8) * Nc + col]     = c2;
            Cz[(size_t)(row + 8) * Nc + col + 1] = c3;
            if (WH) {
                __half2 p0 = __floats2half2_rn(c0, c1);
                __half2 p1 = __floats2half2_rn(c2, c3);
                *(uint32_t*)(g_H16 + (size_t)row * Nc + col) =
                    *reinterpret_cast<uint32_t*>(&p0);
                *(uint32_t*)(g_H16 + (size_t)(row + 8) * Nc + col) =
                    *reinterpret_cast<uint32_t*>(&p1);
            }
        }
    }
}

// ---------------- attention features f1 = h@v0, f2 = h@v1 (dec path) -------
__global__ void __launch_bounds__(512) feats2(const float* __restrict__ Hpre,
                                              const float* __restrict__ v0,
                                              const float* __restrict__ v1) {
    int tid = threadIdx.x, wid = tid >> 5, lid = tid & 31;
    int n = blockIdx.x * 4 + (wid >> 2);
    int h = wid & 3;
    float4 hv = *(const float4*)(Hpre + (size_t)n * HH1 + h * CHAN + lid * 4);
    float4 a  = *(const float4*)(v0 + h * CHAN + lid * 4);
    float4 b  = *(const float4*)(v1 + h * CHAN + lid * 4);
    float s1 = hv.x * a.x + hv.y * a.y + hv.z * a.z + hv.w * a.w;
    float s2 = hv.x * b.x + hv.y * b.y + hv.z * b.z + hv.w * b.w;
#pragma unroll
    for (int o = 16; o > 0; o >>= 1) {
        s1 += __shfl_down_sync(0xffffffffu, s1, o);
        s2 += __shfl_down_sync(0xffffffffu, s2, o);
    }
    if (lid == 0) {
        g_f1[h * NN + n] = s1;
        g_f2[h * NN + n] = s2;
    }
}

// ---------------- sparse attention softmax + aggregation + ELU -------------
// warp = one (row, head); register softmax; gathers fp16 H; writes fp16 A
__global__ void __launch_bounds__(128) gat_agg4() {
    int row = blockIdx.x, tid = threadIdx.x, wid = tid >> 5, lid = tid & 31;
    int cnt = g_cnt[row];
    const int* cols = g_cols + row * CAP;
    const float* f2h = g_f2 + wid * NN;
    float f1r = g_f1[wid * NN + row];
    const __half* Hb = g_H16 + wid * CHAN + lid * 4;
    float4 acc = {0.f, 0.f, 0.f, 0.f};
    float inv;

    if (cnt <= 32) {
        bool valid = lid < cnt;
        int col = valid ? cols[lid] : 0;
        float u = 0.f;
        if (valid) {
            float x = f1r + f2h[col];
            u = 1.f / (1.f + expf(-x)) - 0.5f;
        }
        float mv = (valid && u != 0.f) ? u : -1e30f;
#pragma unroll
        for (int o = 16; o; o >>= 1) mv = fmaxf(mv, __shfl_xor_sync(0xffffffffu, mv, o));
        float e = (valid && u != 0.f) ? expf(u - mv) : 0.f;
        float s = e;
#pragma unroll
        for (int o = 16; o; o >>= 1) s += __shfl_xor_sync(0xffffffffu, s, o);
        inv = 1.f / fmaxf(s, 1e-30f);
        for (int k = 0; k < cnt; k++) {
            float w = __shfl_sync(0xffffffffu, e, k);
            int c2 = __shfl_sync(0xffffffffu, col, k);
            if (w != 0.f) {
                uint2 uv = *(const uint2*)(Hb + (size_t)c2 * HH1);
                float2 f0 = __half22float2(*reinterpret_cast<__half2*>(&uv.x));
                float2 f1v = __half22float2(*reinterpret_cast<__half2*>(&uv.y));
                acc.x += w * f0.x; acc.y += w * f0.y;
                acc.z += w * f1v.x; acc.w += w * f1v.y;
            }
        }
    } else {
        float mv = -1e30f;
        for (int c0 = 0; c0 < cnt; c0 += 32) {
            int k = c0 + lid;
            if (k < cnt) {
                float x = f1r + f2h[cols[k]];
                float u = 1.f / (1.f + expf(-x)) - 0.5f;
                if (u != 0.f) mv = fmaxf(mv, u);
            }
        }
#pragma unroll
        for (int o = 16; o; o >>= 1) mv = fmaxf(mv, __shfl_xor_sync(0xffffffffu, mv, o));
        float s = 0.f;
        for (int c0 = 0; c0 < cnt; c0 += 32) {
            int k = c0 + lid;
            if (k < cnt) {
                float x = f1r + f2h[cols[k]];
                float u = 1.f / (1.f + expf(-x)) - 0.5f;
                if (u != 0.f) s += expf(u - mv);
            }
        }
#pragma unroll
        for (int o = 16; o; o >>= 1) s += __shfl_xor_sync(0xffffffffu, s, o);
        inv = 1.f / fmaxf(s, 1e-30f);
        for (int c0 = 0; c0 < cnt; c0 += 32) {
            int k = c0 + lid;
            int col = (k < cnt) ? cols[k] : 0;
            float e = 0.f;
            if (k < cnt) {
                float x = f1r + f2h[col];
                float u = 1.f / (1.f + expf(-x)) - 0.5f;
                if (u != 0.f) e = expf(u - mv);
            }
            int lim = min(32, cnt - c0);
            for (int j = 0; j < lim; j++) {
                float w = __shfl_sync(0xffffffffu, e, j);
                int c2 = __shfl_sync(0xffffffffu, col, j);
                if (w != 0.f) {
                    uint2 uv = *(const uint2*)(Hb + (size_t)c2 * HH1);
                    float2 f0 = __half22float2(*reinterpret_cast<__half2*>(&uv.x));
                    float2 f1v = __half22float2(*reinterpret_cast<__half2*>(&uv.y));
                    acc.x += w * f0.x; acc.y += w * f0.y;
                    acc.z += w * f1v.x; acc.w += w * f1v.y;
                }
            }
        }
    }

    acc.x *= inv; acc.y *= inv; acc.z *= inv; acc.w *= inv;
    acc.x = (acc.x > 0.f) ? acc.x : expm1f(acc.x);
    acc.y = (acc.y > 0.f) ? acc.y : expm1f(acc.y);
    acc.z = (acc.z > 0.f) ? acc.z : expm1f(acc.z);
    acc.w = (acc.w > 0.f) ? acc.w : expm1f(acc.w);
    __half2 p0 = __floats2half2_rn(acc.x, acc.y);
    __half2 p1 = __floats2half2_rn(acc.z, acc.w);
    uint2 u;
    u.x = *reinterpret_cast<uint32_t*>(&p0);
    u.y = *reinterpret_cast<uint32_t*>(&p1);
    *(uint2*)(g_A16 + (size_t)row * HH1 + wid * CHAN + lid * 4) = u;
}

// ---------------- Hd = concat(Z, emb[slice], zero-pad to 128) -> fp16 ------
__global__ void build_hd(const float* __restrict__ Z,
                         const int* __restrict__ slice,
                         const float* __restrict__ emb) {
    int n = blockIdx.x, t = threadIdx.x;  // 128 threads
    float v = 0.f;
    if (t < HH2) v = Z[(size_t)n * HH2 + t];
    else if (t < HH2 + SEDIM) v = emb[slice[n] * SEDIM + (t - HH2)];
    g_A16[(size_t)n * KP_DEC + t] = __float2half_rn(v);
}

extern "C" void kernel_launch(void* const* d_in, const int* in_sizes, int n_in,
                              void* d_out, int out_size) {
    const float* adj     = (const float*)d_in[0];
    const float* node    = (const float*)d_in[1];
    const int*   slice   = (const int*)d_in[4];
    const float* enc1_W  = (const float*)d_in[6];
    const float* enc1_b  = (const float*)d_in[7];
    const float* enc1_v0 = (const float*)d_in[8];
    const float* enc1_v1 = (const float*)d_in[9];
    const float* enc2_W  = (const float*)d_in[10];
    const float* enc2_b  = (const float*)d_in[11];
    const float* dec1_W  = (const float*)d_in[12];
    const float* dec1_b  = (const float*)d_in[13];
    const float* dec1_v0 = (const float*)d_in[14];
    const float* dec1_v1 = (const float*)d_in[15];
    const float* dec2_W  = (const float*)d_in[16];
    const float* dec2_b  = (const float*)d_in[17];
    const float* emb     = (const float*)d_in[18];

    float* out_recon = (float*)d_out;                   // [N, G]
    float* out_Z     = (float*)d_out + (size_t)NN * GG; // [N, H2]

    float* Hpre; cudaGetSymbolAddress((void**)&Hpre, g_Hpre);
    float* P0;   cudaGetSymbolAddress((void**)&P0, g_P0);
    __half* A16; cudaGetSymbolAddress((void**)&A16, g_A16);
    __half* W1h; cudaGetSymbolAddress((void**)&W1h, g_W1h);
    __half* W1l; cudaGetSymbolAddress((void**)&W1l, g_W1l);
    __half* W2h; cudaGetSymbolAddress((void**)&W2h, g_W2h);
    __half* W2l; cudaGetSymbolAddress((void**)&W2l, g_W2l);
    __half* W3h; cudaGetSymbolAddress((void**)&W3h, g_W3h);
    __half* W3l; cudaGetSymbolAddress((void**)&W3l, g_W3l);
    __half* W4h; cudaGetSymbolAddress((void**)&W4h, g_W4h);
    __half* W4l; cudaGetSymbolAddress((void**)&W4l, g_W4l);

    const int SM128 = 2 * (128 * 80 + 2 * 128 * 80); // 61440
    const int SM64  = 2 * (128 * 80 + 2 * 64 * 80);  // 40960
    cudaFuncSetAttribute((const void*)gemm2<128, 128, false>,
                         cudaFuncAttributeMaxDynamicSharedMemorySize, SM128);
    cudaFuncSetAttribute((const void*)gemm2<128, 128, true>,
                         cudaFuncAttributeMaxDynamicSharedMemorySize, SM128);
    cudaFuncSetAttribute((const void*)gemm2<128, 64, false>,
                         cudaFuncAttributeMaxDynamicSharedMemorySize, SM64);

    // 0. fused prologue: CSR + fp16 convert + all weight packs
    prologue<<<12672, 256>>>(adj, (const float4*)node,
                             enc1_W, enc2_W, dec1_W, dec2_W);

    // 1. enc1 GEMM (K=1024, split-K=2) + fused reduce->H16 + feats
    gemm2<128, 128, false><<<dim3(4, 32, 2), 256, SM128>>>(
        A16, W1h, W1l, nullptr, P0, GG, GG / 2, HH1);
    reduceF<<<NN * HH1 / 4 / 256, 256>>>(
        (const float4*)P0, (const float4*)enc1_b,
        (const float4*)enc1_v0, (const float4*)enc1_v1);
    gat_agg4<<<NN, 128>>>();   // H16 -> g_A16 [4096,512] fp16

    // 2. Z GEMM (K=512, split-K=4) + reduce into output tail
    gemm2<128, 64, false><<<dim3(1, 32, 4), 256, SM64>>>(
        A16, W2h, W2l, nullptr, P0, HH1, HH1 / 4, HH2);
    reduceP<<<(NN * HH2 / 4 + 255) / 256, 256>>>(
        (const float4*)P0, (float4*)out_Z, (const float4*)enc2_b, HH2 / 4, 4, NN * HH2 / 4);

    // 3. decoder GAT layer (K=128): GEMM writes Hpre fp32 + H16 fp16
    build_hd<<<NN, 128>>>(out_Z, slice, emb);   // -> g_A16 [4096,128]
    gemm2<128, 128, true><<<dim3(4, 32, 1), 256, SM128>>>(
        A16, W3h, W3l, dec1_b, Hpre, KP_DEC, KP_DEC, HH1);
    feats2<<<NN / 4, 512>>>(Hpre, dec1_v0, dec1_v1);
    gat_agg4<<<NN, 128>>>();   // H16 -> g_A16 [4096,512]

    // 4. recon GEMM (K=512)
    gemm2<128, 128, false><<<dim3(8, 32, 1), 256, SM128>>>(
        A16, W4h, W4l, dec2_b, out_recon, HH1, HH1, GG);
}

// round 12
// speedup vs baseline: 2.2525x; 1.0711x over previous
#include <cuda_runtime.h>
#include <cuda_fp16.h>
#include <math.h>
#include <stdint.h>

#define NN 4096
#define GG 1024
#define HH1 512
#define HH2 64
#define NHEAD 4
#define CHAN 128
#define SEDIM 16
#define CAP 256
#define KP_DEC 128

// ---------------- scratch (static device globals; no allocation) ----------
__device__ __half g_A16[NN * GG];          // activations, single fp16
__device__ __half g_H16[NN * HH1];         // GAT pre-activation H, fp16
__device__ __half g_W1h[HH1 * GG],     g_W1l[HH1 * GG];      // enc1 [512][1024]
__device__ __half g_W2h[HH2 * HH1],    g_W2l[HH2 * HH1];     // enc2 [64][512]
__device__ __half g_W3h[HH1 * KP_DEC], g_W3l[HH1 * KP_DEC];  // dec1 [512][128]
__device__ __half g_W4h[GG * HH1],     g_W4l[GG * HH1];      // dec2 [1024][512]
__device__ float g_P0[NN * GG];            // split-K partials
__device__ float g_f1[NHEAD * NN];
__device__ float g_f2[NHEAD * NN];
__device__ int   g_cols[NN * CAP];
__device__ int   g_cnt[NN];

// ---------------- helpers ---------------------------------------------------
__device__ __forceinline__ void hsplit(float x, __half* h, __half* l) {
    __half hh = __float2half_rn(x);
    *h = hh;
    *l = __float2half_rn(x - __half2float(hh));
}
__device__ __forceinline__ uint32_t smem_u32(const void* p) {
    uint32_t a;
    asm("{ .reg .u64 t; cvta.to.shared.u64 t, %1; cvt.u32.u64 %0, t; }" : "=r"(a) : "l"(p));
    return a;
}
#define LDM4(r, addr) \
    asm volatile("ldmatrix.sync.aligned.m8n8.x4.shared.b16 {%0,%1,%2,%3}, [%4];" \
                 : "=r"((r)[0]), "=r"((r)[1]), "=r"((r)[2]), "=r"((r)[3]) : "r"(addr))
#define MMAF16(d, a, b0_, b1_) \
    asm volatile("mma.sync.aligned.m16n8k16.row.col.f32.f16.f16.f32 " \
                 "{%0,%1,%2,%3}, {%4,%5,%6,%7}, {%8,%9}, {%0,%1,%2,%3};" \
                 : "+f"((d)[0]), "+f"((d)[1]), "+f"((d)[2]), "+f"((d)[3]) \
                 : "r"((a)[0]), "r"((a)[1]), "r"((a)[2]), "r"((a)[3]), "r"(b0_), "r"(b1_))
#define CP16(dst, src) \
    asm volatile("cp.async.cg.shared.global [%0], [%1], 16;" :: "r"(dst), "l"(src))

// ---------------- fused prologue: csr + A16 convert + all weight packs -----
__global__ void __launch_bounds__(256) prologue(
    const float* __restrict__ adj, const float4* __restrict__ node,
    const float* __restrict__ enc1_W, const float* __restrict__ enc2_W,
    const float* __restrict__ dec1_W, const float* __restrict__ dec2_W) {
    __shared__ int cnt;
    int b = blockIdx.x, tid = threadIdx.x;
    if (b < 4096) {
        if (tid == 0) cnt = 0;
        __syncthreads();
        const float4* arow = (const float4*)(adj + (size_t)b * NN);
        for (int j4 = tid; j4 < NN / 4; j4 += 256) {
            float4 v = arow[j4];
            if (v.x != 0.f) { int k = atomicAdd(&cnt, 1); if (k < CAP) g_cols[b * CAP + k] = j4 * 4 + 0; }
            if (v.y != 0.f) { int k = atomicAdd(&cnt, 1); if (k < CAP) g_cols[b * CAP + k] = j4 * 4 + 1; }
            if (v.z != 0.f) { int k = atomicAdd(&cnt, 1); if (k < CAP) g_cols[b * CAP + k] = j4 * 4 + 2; }
            if (v.w != 0.f) { int k = atomicAdd(&cnt, 1); if (k < CAP) g_cols[b * CAP + k] = j4 * 4 + 3; }
        }
        __syncthreads();
        if (tid == 0) g_cnt[b] = min(cnt, CAP);
    } else if (b < 8192) {
        int i = (b - 4096) * 256 + tid;          // over NN*GG/4
        float4 v = node[i];
        __half2 h0 = __floats2half2_rn(v.x, v.y);
        __half2 h1 = __floats2half2_rn(v.z, v.w);
        uint2 u;
        u.x = *reinterpret_cast<uint32_t*>(&h0);
        u.y = *reinterpret_cast<uint32_t*>(&h1);
        *(uint2*)(g_A16 + (size_t)i * 4) = u;
    } else if (b < 10240) {
        int idx = (b - 8192) * 256 + tid;
        int n = idx >> 10, k = idx & 1023;
        float v = enc1_W[((size_t)(n >> 7) * GG + k) * CHAN + (n & 127)];
        hsplit(v, &g_W1h[idx], &g_W1l[idx]);
    } else if (b < 10368) {
        int idx = (b - 10240) * 256 + tid;
        int n = idx >> 9, k = idx & 511;
        hsplit(enc2_W[k * HH2 + n], &g_W2h[idx], &g_W2l[idx]);
    } else if (b < 10624) {
        int idx = (b - 10368) * 256 + tid;
        int n = idx >> 7, k = idx & 127;
        float v = (k < HH2 + SEDIM)
                      ? dec1_W[((size_t)(n >> 7) * (HH2 + SEDIM) + k) * CHAN + (n & 127)]
                      : 0.f;
        hsplit(v, &g_W3h[idx], &g_W3l[idx]);
    } else {
        int idx = (b - 10624) * 256 + tid;
        int n = idx >> 9, k = idx & 511;
        hsplit(dec2_W[(size_t)k * GG + n], &g_W4h[idx], &g_W4l[idx]);
    }
}

// ---------------- enc1 fused reduce: partials + bias -> H16 + f1/f2 --------
__global__ void __launch_bounds__(256) reduceF(
    const float4* __restrict__ P, const float4* __restrict__ bias,
    const float4* __restrict__ v0, const float4* __restrict__ v1) {
    const int idx = blockIdx.x * 256 + threadIdx.x;      // over NN*HH1/4
    const int row = idx >> 7, col4 = idx & 127;
    const int lid = threadIdx.x & 31;
    constexpr int T4 = NN * HH1 / 4;
    float4 s = P[idx];
    float4 q = P[idx + T4];
    s.x += q.x; s.y += q.y; s.z += q.z; s.w += q.w;
    float4 b = bias[col4];
    s.x += b.x; s.y += b.y; s.z += b.z; s.w += b.w;
    __half2 h0 = __floats2half2_rn(s.x, s.y);
    __half2 h1 = __floats2half2_rn(s.z, s.w);
    uint2 u;
    u.x = *reinterpret_cast<uint32_t*>(&h0);
    u.y = *reinterpret_cast<uint32_t*>(&h1);
    *(uint2*)(g_H16 + (size_t)idx * 4) = u;
    float4 a = v0[col4], c = v1[col4];
    float s1 = s.x * a.x + s.y * a.y + s.z * a.z + s.w * a.w;
    float s2 = s.x * c.x + s.y * c.y + s.z * c.z + s.w * c.w;
#pragma unroll
    for (int o = 16; o > 0; o >>= 1) {
        s1 += __shfl_down_sync(0xffffffffu, s1, o);
        s2 += __shfl_down_sync(0xffffffffu, s2, o);
    }
    if (lid == 0) {
        int h = col4 >> 5;
        g_f1[h * NN + row] = s1;
        g_f2[h * NN + row] = s2;
    }
}

// ---------------- fused Z reduce + decoder input build ---------------------
// out_Z[n][c<64] = sum_z P + bias; A16[n][0:64]=Z, [64:80]=emb[slice], [80:128]=0
__global__ void __launch_bounds__(128) reduceZ(
    const float* __restrict__ P, const float* __restrict__ bias,
    float* __restrict__ outZ, const int* __restrict__ slice,
    const float* __restrict__ emb) {
    int n = blockIdx.x, t = threadIdx.x;   // 128 threads
    float v = 0.f;
    if (t < HH2) {
        int e = n * HH2 + t;
        v = P[e] + P[e + NN * HH2] + P[e + 2 * NN * HH2] + P[e + 3 * NN * HH2] + bias[t];
        outZ[e] = v;
    } else if (t < HH2 + SEDIM) {
        v = emb[slice[n] * SEDIM + (t - HH2)];
    }
    g_A16[(size_t)n * KP_DEC + t] = __float2half_rn(v);
}

// ---------------- HMMA fp16 2-term GEMM, 3-stage pipeline, 1 sync/chunk -----
// MODE 0: write C fp32 (+bias or raw partial).  MODE 2: write H16 only (+bias).
template <int MTILE, int NT, int MODE>
__global__ void __launch_bounds__(256, 2)
gemm2(const __half* __restrict__ A, const __half* __restrict__ Bh_,
      const __half* __restrict__ Bl_, const float* __restrict__ bias,
      float* __restrict__ C, int Kfull, int Ksplit, int Nc) {
    constexpr int WMW = 2;
    constexpr int WNW = 4;
    constexpr int WM  = MTILE / WMW;             // 64
    constexpr int WN  = NT / WNW;
    constexpr int MT  = WM / 16;                 // 4
    constexpr int NTL = WN / 8;
    constexpr int NP  = NTL / 2;
    constexpr int ASZ = MTILE * 80;
    constexpr int BSZ = NT * 80;
    constexpr int STG = ASZ + 2 * BSZ;
    constexpr int AJ  = MTILE / 64;              // 2
    constexpr int BJ  = NT / 64;

    extern __shared__ char sm[];
    const int tid = threadIdx.x, lane = tid & 31, wid = tid >> 5;
    const int m0 = blockIdx.y * MTILE, n0 = blockIdx.x * NT;
    const int koff = blockIdx.z * Ksplit;
    const int wm0 = (wid % WMW) * WM, wn0 = (wid / WMW) * WN;

    const int ar = tid >> 1, ac = (tid & 1) * 16;
    const size_t abase = (size_t)(m0 + ar) * Kfull + koff + ac;
    const int br = (BJ == 2) ? (tid >> 1) : (tid >> 2);
    const int bc = (BJ == 2) ? ((tid & 1) * 16) : ((tid & 3) * 8);
    const size_t bbase = (size_t)(n0 + br) * Kfull + koff + bc;

    const uint32_t sA = smem_u32(sm);
    const uint32_t stA = ar * 80 + ac * 2;
    const uint32_t stB = br * 80 + bc * 2;

    const int lr = lane & 15, lk = (lane >> 4) * 8;
    const uint32_t aoff = (wm0 + lr) * 80 + lk * 2;
    const uint32_t boff = (wn0 + lr) * 80 + lk * 2;

    float acc[MT][NTL][4];
#pragma unroll
    for (int i = 0; i < MT; i++)
#pragma unroll
        for (int j = 0; j < NTL; j++)
#pragma unroll
            for (int q = 0; q < 4; q++) acc[i][j][q] = 0.f;

    const int NC = Ksplit >> 5;

#define GLOADC(c0, buf)                                                        \
    {                                                                          \
        int k0 = (c0) * 32;                                                    \
        uint32_t d = sA + (buf) * STG;                                         \
        _Pragma("unroll") for (int j = 0; j < AJ; j++)                         \
            CP16(d + stA + j * 16, A + abase + k0 + j * 8);                    \
        _Pragma("unroll") for (int j = 0; j < BJ; j++) {                       \
            CP16(d + ASZ + stB + j * 16, Bh_ + bbase + k0 + j * 8);            \
            CP16(d + ASZ + BSZ + stB + j * 16, Bl_ + bbase + k0 + j * 8);      \
        }                                                                      \
        asm volatile("cp.async.commit_group;" ::: "memory");                   \
    }

    GLOADC(0, 0);
    GLOADC(1, 1);
    for (int c = 0; c < NC; c++) {
        if (c + 1 < NC) {
            asm volatile("cp.async.wait_group 1;" ::: "memory");
        } else {
            asm volatile("cp.async.wait_group 0;" ::: "memory");
        }
        __syncthreads();                 // single barrier per chunk
        int buf = c % 3;
        uint32_t uA  = sA + buf * STG;
        uint32_t uBh = uA + ASZ;
        uint32_t uBl = uBh + BSZ;
#pragma unroll
        for (int ks = 0; ks < 2; ks++) {
            uint32_t a_[MT][4], bh[NP][4], bl[NP][4];
#pragma unroll
            for (int mt = 0; mt < MT; mt++) LDM4(a_[mt], uA + aoff + mt * 1280 + ks * 32);
#pragma unroll
            for (int p = 0; p < NP; p++) LDM4(bh[p], uBh + boff + p * 1280 + ks * 32);
#pragma unroll
            for (int p = 0; p < NP; p++) LDM4(bl[p], uBl + boff + p * 1280 + ks * 32);
#pragma unroll
            for (int mt = 0; mt < MT; mt++)
#pragma unroll
                for (int p = 0; p < NP; p++) {
                    MMAF16(acc[mt][2 * p],     a_[mt], bh[p][0], bh[p][2]);
                    MMAF16(acc[mt][2 * p + 1], a_[mt], bh[p][1], bh[p][3]);
                }
#pragma unroll
            for (int mt = 0; mt < MT; mt++)
#pragma unroll
                for (int p = 0; p < NP; p++) {
                    MMAF16(acc[mt][2 * p],     a_[mt], bl[p][0], bl[p][2]);
                    MMAF16(acc[mt][2 * p + 1], a_[mt], bl[p][1], bl[p][3]);
                }
        }
        if (c + 2 < NC) GLOADC(c + 2, (c + 2) % 3);
    }
#undef GLOADC

    // epilogue
    float* Cz = C + (size_t)blockIdx.z * NN * Nc;
    int g = lane >> 2, tg = lane & 3;
#pragma unroll
    for (int mt = 0; mt < MT; mt++) {
        int row = m0 + wm0 + mt * 16 + g;
#pragma unroll
        for (int nt = 0; nt < NTL; nt++) {
            int col = n0 + wn0 + nt * 8 + tg * 2;
            float b0 = bias ? bias[col] : 0.f, b1 = bias ? bias[col + 1] : 0.f;
            float c0 = acc[mt][nt][0] + b0, c1 = acc[mt][nt][1] + b1;
            float c2 = acc[mt][nt][2] + b0, c3 = acc[mt][nt][3] + b1;
            if (MODE == 0) {
                Cz[(size_t)row * Nc + col]           = c0;
                Cz[(size_t)row * Nc + col + 1]       = c1;
                Cz[(size_t)(row + 8) * Nc + col]     = c2;
                Cz[(size_t)(row + 8) * Nc + col + 1] = c3;
            } else {
                __half2 p0 = __floats2half2_rn(c0, c1);
                __half2 p1 = __floats2half2_rn(c2, c3);
                *(uint32_t*)(g_H16 + (size_t)row * Nc + col) =
                    *reinterpret_cast<uint32_t*>(&p0);
                *(uint32_t*)(g_H16 + (size_t)(row + 8) * Nc + col) =
                    *reinterpret_cast<uint32_t*>(&p1);
            }
        }
    }
}

// ---------------- attention features from fp16 H (dec path) ----------------
__global__ void __launch_bounds__(512) feats2h(const float* __restrict__ v0,
                                               const float* __restrict__ v1) {
    int tid = threadIdx.x, wid = tid >> 5, lid = tid & 31;
    int n = blockIdx.x * 4 + (wid >> 2);
    int h = wid & 3;
    uint2 uv = *(const uint2*)(g_H16 + (size_t)n * HH1 + h * CHAN + lid * 4);
    float2 f0 = __half22float2(*reinterpret_cast<__half2*>(&uv.x));
    float2 f1v = __half22float2(*reinterpret_cast<__half2*>(&uv.y));
    float4 a = *(const float4*)(v0 + h * CHAN + lid * 4);
    float4 b = *(const float4*)(v1 + h * CHAN + lid * 4);
    float s1 = f0.x * a.x + f0.y * a.y + f1v.x * a.z + f1v.y * a.w;
    float s2 = f0.x * b.x + f0.y * b.y + f1v.x * b.z + f1v.y * b.w;
#pragma unroll
    for (int o = 16; o > 0; o >>= 1) {
        s1 += __shfl_down_sync(0xffffffffu, s1, o);
        s2 += __shfl_down_sync(0xffffffffu, s2, o);
    }
    if (lid == 0) {
        g_f1[h * NN + n] = s1;
        g_f2[h * NN + n] = s2;
    }
}

// ---------------- sparse attention softmax + aggregation + ELU -------------
__global__ void __launch_bounds__(128) gat_agg4() {
    int row = blockIdx.x, tid = threadIdx.x, wid = tid >> 5, lid = tid & 31;
    int cnt = g_cnt[row];
    const int* cols = g_cols + row * CAP;
    const float* f2h = g_f2 + wid * NN;
    float f1r = g_f1[wid * NN + row];
    const __half* Hb = g_H16 + wid * CHAN + lid * 4;
    float4 acc = {0.f, 0.f, 0.f, 0.f};
    float inv;

    if (cnt <= 32) {
        bool valid = lid < cnt;
        int col = valid ? cols[lid] : 0;
        float u = 0.f;
        if (valid) {
            float x = f1r + f2h[col];
            u = 1.f / (1.f + expf(-x)) - 0.5f;
        }
        float mv = (valid && u != 0.f) ? u : -1e30f;
#pragma unroll
        for (int o = 16; o; o >>= 1) mv = fmaxf(mv, __shfl_xor_sync(0xffffffffu, mv, o));
        float e = (valid && u != 0.f) ? expf(u - mv) : 0.f;
        float s = e;
#pragma unroll
        for (int o = 16; o; o >>= 1) s += __shfl_xor_sync(0xffffffffu, s, o);
        inv = 1.f / fmaxf(s, 1e-30f);
        // pack (fp16 weight, col) into one word -> 1 shfl per neighbor
        uint32_t pk = ((uint32_t)__half_as_ushort(__float2half_rn(e)) << 16) |
                      (uint32_t)col;
        for (int k = 0; k < cnt; k++) {
            uint32_t p = __shfl_sync(0xffffffffu, pk, k);
            if (p >> 16) {
                float w = __half2float(__ushort_as_half((unsigned short)(p >> 16)));
                int c2 = p & 0xFFFF;
                uint2 uv = *(const uint2*)(Hb + (size_t)c2 * HH1);
                float2 f0 = __half22float2(*reinterpret_cast<__half2*>(&uv.x));
                float2 f1v = __half22float2(*reinterpret_cast<__half2*>(&uv.y));
                acc.x += w * f0.x; acc.y += w * f0.y;
                acc.z += w * f1v.x; acc.w += w * f1v.y;
            }
        }
    } else {
        float mv = -1e30f;
        for (int c0 = 0; c0 < cnt; c0 += 32) {
            int k = c0 + lid;
            if (k < cnt) {
                float x = f1r + f2h[cols[k]];
                float u = 1.f / (1.f + expf(-x)) - 0.5f;
                if (u != 0.f) mv = fmaxf(mv, u);
            }
        }
#pragma unroll
        for (int o = 16; o; o >>= 1) mv = fmaxf(mv, __shfl_xor_sync(0xffffffffu, mv, o));
        float s = 0.f;
        for (int c0 = 0; c0 < cnt; c0 += 32) {
            int k = c0 + lid;
            if (k < cnt) {
                float x = f1r + f2h[cols[k]];
                float u = 1.f / (1.f + expf(-x)) - 0.5f;
                if (u != 0.f) s += expf(u - mv);
            }
        }
#pragma unroll
        for (int o = 16; o; o >>= 1) s += __shfl_xor_sync(0xffffffffu, s, o);
        inv = 1.f / fmaxf(s, 1e-30f);
        for (int c0 = 0; c0 < cnt; c0 += 32) {
            int k = c0 + lid;
            int col = (k < cnt) ? cols[k] : 0;
            float e = 0.f;
            if (k < cnt) {
                float x = f1r + f2h[col];
                float u = 1.f / (1.f + expf(-x)) - 0.5f;
                if (u != 0.f) e = expf(u - mv);
            }
            int lim = min(32, cnt - c0);
            for (int j = 0; j < lim; j++) {
                float w = __shfl_sync(0xffffffffu, e, j);
                int c2 = __shfl_sync(0xffffffffu, col, j);
                if (w != 0.f) {
                    uint2 uv = *(const uint2*)(Hb + (size_t)c2 * HH1);
                    float2 f0 = __half22float2(*reinterpret_cast<__half2*>(&uv.x));
                    float2 f1v = __half22float2(*reinterpret_cast<__half2*>(&uv.y));
                    acc.x += w * f0.x; acc.y += w * f0.y;
                    acc.z += w * f1v.x; acc.w += w * f1v.y;
                }
            }
        }
    }

    acc.x *= inv; acc.y *= inv; acc.z *= inv; acc.w *= inv;
    acc.x = (acc.x > 0.f) ? acc.x : expm1f(acc.x);
    acc.y = (acc.y > 0.f) ? acc.y : expm1f(acc.y);
    acc.z = (acc.z > 0.f) ? acc.z : expm1f(acc.z);
    acc.w = (acc.w > 0.f) ? acc.w : expm1f(acc.w);
    __half2 p0 = __floats2half2_rn(acc.x, acc.y);
    __half2 p1 = __floats2half2_rn(acc.z, acc.w);
    uint2 u;
    u.x = *reinterpret_cast<uint32_t*>(&p0);
    u.y = *reinterpret_cast<uint32_t*>(&p1);
    *(uint2*)(g_A16 + (size_t)row * HH1 + wid * CHAN + lid * 4) = u;
}

extern "C" void kernel_launch(void* const* d_in, const int* in_sizes, int n_in,
                              void* d_out, int out_size) {
    const float* adj     = (const float*)d_in[0];
    const float* node    = (const float*)d_in[1];
    const int*   slice   = (const int*)d_in[4];
    const float* enc1_W  = (const float*)d_in[6];
    const float* enc1_b  = (const float*)d_in[7];
    const float* enc1_v0 = (const float*)d_in[8];
    const float* enc1_v1 = (const float*)d_in[9];
    const float* enc2_W  = (const float*)d_in[10];
    const float* enc2_b  = (const float*)d_in[11];
    const float* dec1_W  = (const float*)d_in[12];
    const float* dec1_b  = (const float*)d_in[13];
    const float* dec1_v0 = (const float*)d_in[14];
    const float* dec1_v1 = (const float*)d_in[15];
    const float* dec2_W  = (const float*)d_in[16];
    const float* dec2_b  = (const float*)d_in[17];
    const float* emb     = (const float*)d_in[18];

    float* out_recon = (float*)d_out;                   // [N, G]
    float* out_Z     = (float*)d_out + (size_t)NN * GG; // [N, H2]

    float* P0;   cudaGetSymbolAddress((void**)&P0, g_P0);
    __half* A16; cudaGetSymbolAddress((void**)&A16, g_A16);
    __half* W1h; cudaGetSymbolAddress((void**)&W1h, g_W1h);
    __half* W1l; cudaGetSymbolAddress((void**)&W1l, g_W1l);
    __half* W2h; cudaGetSymbolAddress((void**)&W2h, g_W2h);
    __half* W2l; cudaGetSymbolAddress((void**)&W2l, g_W2l);
    __half* W3h; cudaGetSymbolAddress((void**)&W3h, g_W3h);
    __half* W3l; cudaGetSymbolAddress((void**)&W3l, g_W3l);
    __half* W4h; cudaGetSymbolAddress((void**)&W4h, g_W4h);
    __half* W4l; cudaGetSymbolAddress((void**)&W4l, g_W4l);

    const int SM128 = 3 * (128 * 80 + 2 * 128 * 80); // 92160
    const int SM64  = 3 * (128 * 80 + 2 * 64 * 80);  // 61440
    cudaFuncSetAttribute((const void*)gemm2<128, 128, 0>,
                         cudaFuncAttributeMaxDynamicSharedMemorySize, SM128);
    cudaFuncSetAttribute((const void*)gemm2<128, 128, 2>,
                         cudaFuncAttributeMaxDynamicSharedMemorySize, SM128);
    cudaFuncSetAttribute((const void*)gemm2<128, 64, 0>,
                         cudaFuncAttributeMaxDynamicSharedMemorySize, SM64);

    // 0. fused prologue: CSR + fp16 convert + all weight packs
    prologue<<<12672, 256>>>(adj, (const float4*)node,
                             enc1_W, enc2_W, dec1_W, dec2_W);

    // 1. enc1 GEMM (K=1024, split-K=2) + fused reduce->H16 + feats
    gemm2<128, 128, 0><<<dim3(4, 32, 2), 256, SM128>>>(
        A16, W1h, W1l, nullptr, P0, GG, GG / 2, HH1);
    reduceF<<<NN * HH1 / 4 / 256, 256>>>(
        (const float4*)P0, (const float4*)enc1_b,
        (const float4*)enc1_v0, (const float4*)enc1_v1);
    gat_agg4<<<NN, 128>>>();   // H16 -> g_A16 [4096,512] fp16

    // 2. Z GEMM (K=512, split-K=4) + fused reduce -> out_Z + decoder input
    gemm2<128, 64, 0><<<dim3(1, 32, 4), 256, SM64>>>(
        A16, W2h, W2l, nullptr, P0, HH1, HH1 / 4, HH2);
    reduceZ<<<NN, 128>>>(P0, enc2_b, out_Z, slice, emb);

    // 3. decoder GAT layer (K=128): GEMM writes H16 only
    gemm2<128, 128, 2><<<dim3(4, 32, 1), 256, SM128>>>(
        A16, W3h, W3l, dec1_b, nullptr, KP_DEC, KP_DEC, HH1);
    feats2h<<<NN / 4, 512>>>(dec1_v0, dec1_v1);
    gat_agg4<<<NN, 128>>>();   // H16 -> g_A16 [4096,512]

    // 4. recon GEMM (K=512)
    gemm2<128, 128, 0><<<dim3(8, 32, 1), 256, SM128>>>(
        A16, W4h, W4l, dec2_b, out_recon, HH1, HH1, GG);
}